// round 5
// baseline (speedup 1.0000x reference)
#include <cuda_runtime.h>
#include <math.h>
#include <stdint.h>

typedef uint32_t u32;
typedef uint64_t u64;

#define T_LEN 262144
#define B_N 8
#define C_N 8
#define K_N 50
#define TILE_M 256     // time rows per block
#define WROWS 64       // time rows per warp (4 m16 subtiles)
#define ROWPAD 12      // floats per SMEM row (48B: ldmatrix conflict-free)

// Ping-pong hidden state [B][C][T]
__device__ float g_h0[B_N * C_N * T_LEN];
__device__ float g_h1[B_N * C_N * T_LEN];
// Layer-0 scalar weights [k][o]
__device__ float g_W0[K_N * C_N];
// Layers 1..17 B fragments: [layer][hl(hi,lo)][tap][lane][2]
__device__ float g_Bfrag[17 * 2 * K_N * 64];

// ---------------------------------------------------------------------------
__device__ __forceinline__ u32 smem_u32(const void* p) {
    return (u32)__cvta_generic_to_shared(p);
}
__device__ __forceinline__ float tf32_hi(float x) {
    return __uint_as_float(__float_as_uint(x) & 0xFFFFE000u);
}
// cvt.rna.tf32.f32 requires a b32 destination register.
__device__ __forceinline__ u32 to_tf32_bits(float x) {
    u32 r;
    asm("cvt.rna.tf32.f32 %0, %1;" : "=r"(r) : "f"(x));
    return r;
}
__device__ __forceinline__ void ldmA(u32& a0, u32& a1, u32& a2, u32& a3, u32 addr) {
    asm volatile("ldmatrix.sync.aligned.m8n8.x4.shared.b16 {%0,%1,%2,%3}, [%4];"
                 : "=r"(a0), "=r"(a1), "=r"(a2), "=r"(a3) : "r"(addr));
}
__device__ __forceinline__ void mma8(float* c, u32 a0, u32 a1, u32 a2, u32 a3,
                                     u32 b0, u32 b1) {
    asm volatile("mma.sync.aligned.m16n8k8.row.col.f32.tf32.tf32.f32 "
                 "{%0,%1,%2,%3},{%4,%5,%6,%7},{%8,%9},{%0,%1,%2,%3};"
                 : "+f"(c[0]), "+f"(c[1]), "+f"(c[2]), "+f"(c[3])
                 : "r"(a0), "r"(a1), "r"(a2), "r"(a3), "r"(b0), "r"(b1));
}
__device__ __forceinline__ float fast_tanh(float x) {
    x = fminf(fmaxf(x, -30.0f), 30.0f);
    float e = __expf(-2.0f * x);
    return (1.0f - e) / (1.0f + e);
}
__device__ __forceinline__ float fast_sigmoid(float x) {
    x = fminf(fmaxf(x, -30.0f), 30.0f);
    return 1.0f / (1.0f + __expf(-x));
}

// ---------------------------------------------------------------------------
// Weight prep: weight-norm; layer0 scalar weights + hi/lo tf32 B fragments.
// B[c][o] for tap j = w[o, c, k=K-1-j].  Fragment slot for (o,c):
//   lane = o*4 + (c&3), reg = c>>2.
// ---------------------------------------------------------------------------
__global__ void prep_weights(const float* __restrict__ v0,
                             const float* __restrict__ g0,
                             const float* __restrict__ vs,
                             const float* __restrict__ gs) {
    int l = blockIdx.x;   // 0..17
    int o = blockIdx.y;   // 0..7
    int cin = (l == 0) ? 1 : C_N;
    const float* v;
    float g;
    if (l == 0) {
        v = v0 + o * K_N;
        g = g0[o];
    } else {
        v = vs + (size_t)((l - 1) * C_N + o) * C_N * K_N;
        g = gs[(l - 1) * C_N + o];
    }
    int n = cin * K_N;
    float s = 0.0f;
    for (int i = threadIdx.x; i < n; i += blockDim.x) {
        float x = v[i];
        s += x * x;
    }
    __shared__ float red[2];
    #pragma unroll
    for (int off = 16; off > 0; off >>= 1)
        s += __shfl_down_sync(0xffffffffu, s, off);
    if ((threadIdx.x & 31) == 0) red[threadIdx.x >> 5] = s;
    __syncthreads();
    float scale = g * rsqrtf(red[0] + red[1]);

    if (l == 0) {
        for (int i = threadIdx.x; i < n; i += blockDim.x)
            g_W0[i * C_N + o] = scale * v[i];   // i == k
    } else {
        float* base = g_Bfrag + (size_t)(l - 1) * 2 * K_N * 64;
        for (int i = threadIdx.x; i < n; i += blockDim.x) {
            int c = i / K_N;
            int k = i % K_N;
            int j = (K_N - 1) - k;             // tap age
            float w = scale * v[i];
            float hi = tf32_hi(w);
            u32 lo = to_tf32_bits(w - hi);
            int slot = j * 64 + (o * 4 + (c & 3)) * 2 + (c >> 2);
            base[slot] = hi;                           // hl = 0
            base[K_N * 64 + slot] = __uint_as_float(lo); // hl = 1
        }
    }
}

// ---------------------------------------------------------------------------
// Layer 0 (scalar; C_in = 1, dilation 1)
// ---------------------------------------------------------------------------
__global__ void __launch_bounds__(128)
layer0_kernel(const float* __restrict__ h_in, float* __restrict__ h_out,
              const float* __restrict__ bias, const float* __restrict__ gw,
              const float* __restrict__ gb) {
    constexpr int NP = 4;
    constexpr int TILE = 128 * NP;
    constexpr int HALO = K_N - 1;
    constexpr int HW = TILE + HALO;

    __shared__ __align__(16) float h_s[HW];
    __shared__ __align__(16) float w_s[K_N][C_N];
    __shared__ float gw_s[C_N][C_N];
    __shared__ float b_s[C_N];
    __shared__ float gb_s[C_N];

    const int b = blockIdx.y;
    const int tile0 = blockIdx.x * TILE;
    const int tid = threadIdx.x;

    for (int i = tid; i < K_N * C_N; i += 128) (&w_s[0][0])[i] = g_W0[i];
    for (int i = tid; i < C_N * C_N; i += 128) (&gw_s[0][0])[i] = gw[i];
    if (tid < C_N) { b_s[tid] = bias[tid]; gb_s[tid] = gb[tid]; }

    const float* hb = h_in + (size_t)b * T_LEN;
    for (int j = tid; j < HW; j += 128) {
        int t = tile0 - HALO + j;
        h_s[j] = (t >= 0) ? hb[t] : 0.0f;
    }
    __syncthreads();

    float acc[C_N][NP];
    #pragma unroll
    for (int o = 0; o < C_N; o++) {
        float bv = b_s[o];
        #pragma unroll
        for (int p = 0; p < NP; p++) acc[o][p] = bv;
    }

    #pragma unroll 1
    for (int k = 0; k < K_N; k++) {
        float hv[NP];
        #pragma unroll
        for (int p = 0; p < NP; p++) hv[p] = h_s[tid + k + p * 128];
        float wv[C_N];
        *(float4*)&wv[0] = *(const float4*)&w_s[k][0];
        *(float4*)&wv[4] = *(const float4*)&w_s[k][4];
        #pragma unroll
        for (int o = 0; o < C_N; o++)
            #pragma unroll
            for (int p = 0; p < NP; p++)
                acc[o][p] = fmaf(wv[o], hv[p], acc[o][p]);
    }

    float* ob = h_out + (size_t)b * C_N * T_LEN;
    #pragma unroll
    for (int p = 0; p < NP; p++) {
        float prev = h_s[tid + HALO + p * 128];
        #pragma unroll
        for (int o = 0; o < C_N; o++) {
            float gate = gb_s[o];
            #pragma unroll
            for (int c = 0; c < C_N; c++) gate = fmaf(gw_s[o][c], acc[c][p], gate);
            ob[(size_t)o * T_LEN + tile0 + tid + p * 128] =
                fast_tanh(acc[o][p]) * fast_sigmoid(gate) + prev;
        }
    }
}

// ---------------------------------------------------------------------------
// Layers 1..17: tf32 mma.sync, hi/lo 3-pass split.
// Block = 128 threads (4 warps), TILE_M=256 time rows; warp w owns rows
// [64w, 64w+64) as 4 m16 subtiles.  A tiles (hi, lo) in dynamic SMEM,
// rows padded to 48B (conflict-free ldmatrix).
// ---------------------------------------------------------------------------
template <int DIL>
__global__ void __launch_bounds__(128)
layer_mma(const float* __restrict__ h_in, float* __restrict__ h_out,
          const float* __restrict__ Bfrag,   // [2][K][64][2] floats
          const float* __restrict__ bias, const float* __restrict__ gw,
          const float* __restrict__ gb) {
    constexpr int HALO = (K_N - 1) * DIL;
    constexpr int HW = TILE_M + HALO;

    extern __shared__ float dyn[];           // hi[HW*12], lo[HW*12]
    float* h_hi = dyn;
    float* h_lo = dyn + HW * ROWPAD;
    __shared__ float ctrl[80];               // bias[8], gb[8], gw[64]

    const int b = blockIdx.y;
    const int tile0 = blockIdx.x * TILE_M;
    const int tid = threadIdx.x;
    const int wid = tid >> 5;
    const int lane = tid & 31;

    if (tid < 8) ctrl[tid] = bias[tid];
    else if (tid < 16) ctrl[tid] = gb[tid - 8];
    else if (tid < 80) ctrl[tid] = gw[tid - 16];

    // Stage hi/lo tiles (coalesced gmem reads, per-channel columns).
    const float* hb = h_in + (size_t)b * C_N * T_LEN;
    #pragma unroll
    for (int c = 0; c < C_N; c++) {
        const float* hc = hb + (size_t)c * T_LEN;
        for (int r = tid; r < HW; r += 128) {
            int t = tile0 - HALO + r;
            float v = (t >= 0) ? hc[t] : 0.0f;
            float hi = tf32_hi(v);
            h_hi[r * ROWPAD + c] = hi;
            h_lo[r * ROWPAD + c] = __uint_as_float(to_tf32_bits(v - hi));
        }
    }
    __syncthreads();

    const u32 hi_base = smem_u32(h_hi);
    const u32 lo_base = smem_u32(h_lo);
    const u32 frag_off = ((lane & 15) * ROWPAD + (lane >> 4) * 4) * 4;

    float acc[4][4];
    #pragma unroll
    for (int s = 0; s < 4; s++)
        #pragma unroll
        for (int q = 0; q < 4; q++) acc[s][q] = 0.0f;

    #pragma unroll 1
    for (int pass = 0; pass < 3; pass++) {
        const u32 abase = (pass == 1) ? lo_base : hi_base;
        const float* bf = Bfrag + ((pass == 2) ? K_N * 64 : 0) + lane * 2;
        u32 addr = abase + (u32)(HALO + wid * WROWS) * (ROWPAD * 4) + frag_off;
        #pragma unroll 2
        for (int j = 0; j < K_N; j++) {
            float2 bb = *(const float2*)(bf + j * 64);
            u32 b0 = __float_as_uint(bb.x);
            u32 b1 = __float_as_uint(bb.y);
            #pragma unroll
            for (int s = 0; s < 4; s++) {
                u32 a0, a1, a2, a3;
                ldmA(a0, a1, a2, a3, addr + (u32)(s * 16 * ROWPAD * 4));
                mma8(acc[s], a0, a1, a2, a3, b0, b1);
            }
            addr -= (u32)(DIL * ROWPAD * 4);
        }
    }

    // Park conv outputs in SMEM (reuse hi tile region as [TILE_M][12]).
    __syncthreads();
    {
        const int gid = lane >> 2;
        const int c0 = (lane & 3) * 2;
        #pragma unroll
        for (int s = 0; s < 4; s++) {
            int rA = wid * WROWS + s * 16 + gid;
            *(float2*)&h_hi[rA * ROWPAD + c0] = make_float2(acc[s][0], acc[s][1]);
            *(float2*)&h_hi[(rA + 8) * ROWPAD + c0] = make_float2(acc[s][2], acc[s][3]);
        }
    }
    __syncthreads();

    // Epilogue: rows tid and tid+128 (coalesced gmem).
    float* ob = h_out + (size_t)b * C_N * T_LEN;
    #pragma unroll
    for (int half = 0; half < 2; half++) {
        const int r = tid + half * 128;
        float outv[C_N];
        #pragma unroll
        for (int o = 0; o < C_N; o++) outv[o] = h_hi[r * ROWPAD + o] + ctrl[o];
        #pragma unroll
        for (int o = 0; o < C_N; o++) {
            float gate = ctrl[8 + o];
            #pragma unroll
            for (int c = 0; c < C_N; c++)
                gate = fmaf(ctrl[16 + o * 8 + c], outv[c], gate);
            float prev = hb[(size_t)o * T_LEN + tile0 + r];
            ob[(size_t)o * T_LEN + tile0 + r] =
                fast_tanh(outv[o]) * fast_sigmoid(gate) + prev;
        }
    }
}

// ---------------------------------------------------------------------------
// Head
// ---------------------------------------------------------------------------
__global__ void __launch_bounds__(256)
head_kernel(const float* __restrict__ h,
            const float* __restrict__ mean_w, const float* __restrict__ mean_b,
            const float* __restrict__ lv_w, const float* __restrict__ lv_b,
            float* __restrict__ out) {
    const int b = blockIdx.y;
    const int t0 = (blockIdx.x * 256 + threadIdx.x) * 4;
    if (t0 >= T_LEN) return;
    const float* hbp = h + (size_t)b * C_N * T_LEN;
    float m[4], lv[4];
    float mb = mean_b[0], lb = lv_b[0];
    #pragma unroll
    for (int p = 0; p < 4; p++) { m[p] = mb; lv[p] = lb; }
    #pragma unroll
    for (int c = 0; c < C_N; c++) {
        float4 hv = *(const float4*)&hbp[(size_t)c * T_LEN + t0];
        float mw = mean_w[c], lw = lv_w[c];
        m[0] = fmaf(mw, hv.x, m[0]); lv[0] = fmaf(lw, hv.x, lv[0]);
        m[1] = fmaf(mw, hv.y, m[1]); lv[1] = fmaf(lw, hv.y, lv[1]);
        m[2] = fmaf(mw, hv.z, m[2]); lv[2] = fmaf(lw, hv.z, lv[2]);
        m[3] = fmaf(mw, hv.w, m[3]); lv[3] = fmaf(lw, hv.w, lv[3]);
    }
    float s[4];
    #pragma unroll
    for (int p = 0; p < 4; p++) s[p] = expf(0.5f * lv[p]);
    *(float4*)&out[(size_t)b * T_LEN + t0] = make_float4(m[0], m[1], m[2], m[3]);
    *(float4*)&out[(size_t)B_N * T_LEN + (size_t)b * T_LEN + t0] =
        make_float4(s[0], s[1], s[2], s[3]);
}

// ---------------------------------------------------------------------------
static int smem_for_dil(int d) {
    int hw = TILE_M + 49 * d;
    return 2 * hw * ROWPAD * 4;
}

extern "C" void kernel_launch(void* const* d_in, const int* in_sizes, int n_in,
                              void* d_out, int out_size) {
    (void)in_sizes; (void)n_in; (void)out_size;
    const float* x      = (const float*)d_in[0];
    const float* v0     = (const float*)d_in[1];
    const float* g0     = (const float*)d_in[2];
    const float* b0     = (const float*)d_in[3];
    const float* gw0    = (const float*)d_in[4];
    const float* gb0    = (const float*)d_in[5];
    const float* vs     = (const float*)d_in[6];
    const float* gs     = (const float*)d_in[7];
    const float* bs     = (const float*)d_in[8];
    const float* gws    = (const float*)d_in[9];
    const float* gbs    = (const float*)d_in[10];
    const float* mean_w = (const float*)d_in[11];
    const float* mean_b = (const float*)d_in[12];
    const float* lv_w   = (const float*)d_in[13];
    const float* lv_b   = (const float*)d_in[14];

    float *bufA, *bufB, *Bfrag;
    cudaGetSymbolAddress((void**)&bufA, g_h0);
    cudaGetSymbolAddress((void**)&bufB, g_h1);
    cudaGetSymbolAddress((void**)&Bfrag, g_Bfrag);

    cudaFuncSetAttribute(layer_mma<1>, cudaFuncAttributeMaxDynamicSharedMemorySize, smem_for_dil(1));
    cudaFuncSetAttribute(layer_mma<2>, cudaFuncAttributeMaxDynamicSharedMemorySize, smem_for_dil(2));
    cudaFuncSetAttribute(layer_mma<4>, cudaFuncAttributeMaxDynamicSharedMemorySize, smem_for_dil(4));
    cudaFuncSetAttribute(layer_mma<8>, cudaFuncAttributeMaxDynamicSharedMemorySize, smem_for_dil(8));

    prep_weights<<<dim3(18, 8), 64>>>(v0, g0, vs, gs);

    layer0_kernel<<<dim3(T_LEN / 512, B_N), 128>>>(x, bufA, b0, gw0, gb0);

    static const int dils[18] = {1,1,1,1,1,1,1,2,2,2,2,4,4,4,4,8,8,8};
    dim3 grid(T_LEN / TILE_M, B_N);
    float* cur = bufA;
    float* nxt = bufB;
    for (int i = 1; i < 18; i++) {
        const float* Wl  = Bfrag + (size_t)(i - 1) * 2 * K_N * 64;
        const float* bl  = bs  + (i - 1) * C_N;
        const float* gwl = gws + (i - 1) * C_N * C_N;
        const float* gbl = gbs + (i - 1) * C_N;
        switch (dils[i]) {
            case 1: layer_mma<1><<<grid, 128, smem_for_dil(1)>>>(cur, nxt, Wl, bl, gwl, gbl); break;
            case 2: layer_mma<2><<<grid, 128, smem_for_dil(2)>>>(cur, nxt, Wl, bl, gwl, gbl); break;
            case 4: layer_mma<4><<<grid, 128, smem_for_dil(4)>>>(cur, nxt, Wl, bl, gwl, gbl); break;
            case 8: layer_mma<8><<<grid, 128, smem_for_dil(8)>>>(cur, nxt, Wl, bl, gwl, gbl); break;
        }
        float* t = cur; cur = nxt; nxt = t;
    }

    head_kernel<<<dim3(T_LEN / (256 * 4), B_N), 256>>>(
        cur, mean_w, mean_b, lv_w, lv_b, (float*)d_out);
}

// round 6
// speedup vs baseline: 1.3138x; 1.3138x over previous
#include <cuda_runtime.h>
#include <cuda_bf16.h>
#include <math.h>
#include <stdint.h>

typedef uint32_t u32;
typedef uint64_t u64;

#define T_LEN 262144
#define B_N 8
#define C_N 8
#define K_N 50
#define TILE_M 256

// Ping-pong hidden state [B][C][T]
__device__ float g_h0[B_N * C_N * T_LEN];
__device__ float g_h1[B_N * C_N * T_LEN];
// Layer-0 scalar weights [k][o]
__device__ float g_W0[K_N * C_N];
// Layers 1..17 B fragments: [layer][hl(hi,lo)][qpair(25)][lane(32)] uint2(b0,b1)
__device__ uint2 g_Bw[17 * 2 * 25 * 32];

// ---------------------------------------------------------------------------
__device__ __forceinline__ u32 smem_u32(const void* p) {
    return (u32)__cvta_generic_to_shared(p);
}
__device__ __forceinline__ void ldmA(u32& a0, u32& a1, u32& a2, u32& a3, u32 addr) {
    asm volatile("ldmatrix.sync.aligned.m8n8.x4.shared.b16 {%0,%1,%2,%3}, [%4];"
                 : "=r"(a0), "=r"(a1), "=r"(a2), "=r"(a3) : "r"(addr));
}
__device__ __forceinline__ void mma16(float* c, u32 a0, u32 a1, u32 a2, u32 a3,
                                      u32 b0, u32 b1) {
    asm volatile("mma.sync.aligned.m16n8k16.row.col.f32.bf16.bf16.f32 "
                 "{%0,%1,%2,%3},{%4,%5,%6,%7},{%8,%9},{%0,%1,%2,%3};"
                 : "+f"(c[0]), "+f"(c[1]), "+f"(c[2]), "+f"(c[3])
                 : "r"(a0), "r"(a1), "r"(a2), "r"(a3), "r"(b0), "r"(b1));
}
__device__ __forceinline__ u32 pack_bf16(float a, float b) {
    __nv_bfloat162 t = __floats2bfloat162_rn(a, b);
    return *(u32*)&t;
}
__device__ __forceinline__ float fast_tanh(float x) {
    x = fminf(fmaxf(x, -30.0f), 30.0f);
    float e = __expf(-2.0f * x);
    return (1.0f - e) / (1.0f + e);
}
__device__ __forceinline__ float fast_sigmoid(float x) {
    x = fminf(fmaxf(x, -30.0f), 30.0f);
    return 1.0f / (1.0f + __expf(-x));
}

// ---------------------------------------------------------------------------
// Weight prep: weight-norm; layer0 scalar weights + bf16 hi/lo tap-pair frags.
// Pair q: MMA k=c (c 0..7)   <-> tap shift s=2q+1 -> w[o][c][48-2q]
//         MMA k=8+c          <-> tap shift s=2q   -> w[o][c][49-2q]
// lane = o*4 + tig: b0 = (B[k=2tig][o], B[k=2tig+1][o]) ; b1 = same at k+8.
// ---------------------------------------------------------------------------
__global__ void prep_weights(const float* __restrict__ v0,
                             const float* __restrict__ g0,
                             const float* __restrict__ vs,
                             const float* __restrict__ gs) {
    int l = blockIdx.x;   // 0..17
    int o = blockIdx.y;   // 0..7
    int cin = (l == 0) ? 1 : C_N;
    const float* v;
    float g;
    if (l == 0) {
        v = v0 + o * K_N;
        g = g0[o];
    } else {
        v = vs + (size_t)((l - 1) * C_N + o) * C_N * K_N;
        g = gs[(l - 1) * C_N + o];
    }
    int n = cin * K_N;
    float s = 0.0f;
    for (int i = threadIdx.x; i < n; i += blockDim.x) {
        float x = v[i];
        s += x * x;
    }
    __shared__ float red[4];
    #pragma unroll
    for (int off = 16; off > 0; off >>= 1)
        s += __shfl_down_sync(0xffffffffu, s, off);
    if ((threadIdx.x & 31) == 0) red[threadIdx.x >> 5] = s;
    __syncthreads();
    float scale = g * rsqrtf(red[0] + red[1] + red[2] + red[3]);

    if (l == 0) {
        for (int i = threadIdx.x; i < n; i += blockDim.x)
            g_W0[i * C_N + o] = scale * v[i];   // i == k
    } else {
        int tid = threadIdx.x;
        if (tid < 100) {
            int q = tid >> 2;
            int tig = tid & 3;
            int k1 = 48 - 2 * q;   // b0 tap
            int k2 = 49 - 2 * q;   // b1 tap
            float wa = scale * v[(2 * tig) * K_N + k1];
            float wb = scale * v[(2 * tig + 1) * K_N + k1];
            float wc = scale * v[(2 * tig) * K_N + k2];
            float wd = scale * v[(2 * tig + 1) * K_N + k2];
            float ha = __bfloat162float(__float2bfloat16_rn(wa));
            float hb = __bfloat162float(__float2bfloat16_rn(wb));
            float hc = __bfloat162float(__float2bfloat16_rn(wc));
            float hd = __bfloat162float(__float2bfloat16_rn(wd));
            size_t base = (size_t)(l - 1) * 1600 + q * 32 + o * 4 + tig;
            g_Bw[base] = make_uint2(pack_bf16(wa, wb), pack_bf16(wc, wd));          // hi
            g_Bw[base + 800] = make_uint2(pack_bf16(wa - ha, wb - hb),
                                          pack_bf16(wc - hc, wd - hd));             // lo
        }
    }
}

// ---------------------------------------------------------------------------
// Layer 0 (scalar; C_in = 1, dilation 1)
// ---------------------------------------------------------------------------
__global__ void __launch_bounds__(128)
layer0_kernel(const float* __restrict__ h_in, float* __restrict__ h_out,
              const float* __restrict__ bias, const float* __restrict__ gw,
              const float* __restrict__ gb) {
    constexpr int NP = 4;
    constexpr int TILE = 128 * NP;
    constexpr int HALO = K_N - 1;
    constexpr int HW = TILE + HALO;

    __shared__ __align__(16) float h_s[HW];
    __shared__ __align__(16) float w_s[K_N][C_N];
    __shared__ float gw_s[C_N][C_N];
    __shared__ float b_s[C_N];
    __shared__ float gb_s[C_N];

    const int b = blockIdx.y;
    const int tile0 = blockIdx.x * TILE;
    const int tid = threadIdx.x;

    for (int i = tid; i < K_N * C_N; i += 128) (&w_s[0][0])[i] = g_W0[i];
    for (int i = tid; i < C_N * C_N; i += 128) (&gw_s[0][0])[i] = gw[i];
    if (tid < C_N) { b_s[tid] = bias[tid]; gb_s[tid] = gb[tid]; }

    const float* hb = h_in + (size_t)b * T_LEN;
    for (int j = tid; j < HW; j += 128) {
        int t = tile0 - HALO + j;
        h_s[j] = (t >= 0) ? hb[t] : 0.0f;
    }
    __syncthreads();

    float acc[C_N][NP];
    #pragma unroll
    for (int o = 0; o < C_N; o++) {
        float bv = b_s[o];
        #pragma unroll
        for (int p = 0; p < NP; p++) acc[o][p] = bv;
    }

    #pragma unroll 1
    for (int k = 0; k < K_N; k++) {
        float hv[NP];
        #pragma unroll
        for (int p = 0; p < NP; p++) hv[p] = h_s[tid + k + p * 128];
        float wv[C_N];
        *(float4*)&wv[0] = *(const float4*)&w_s[k][0];
        *(float4*)&wv[4] = *(const float4*)&w_s[k][4];
        #pragma unroll
        for (int o = 0; o < C_N; o++)
            #pragma unroll
            for (int p = 0; p < NP; p++)
                acc[o][p] = fmaf(wv[o], hv[p], acc[o][p]);
    }

    float* ob = h_out + (size_t)b * C_N * T_LEN;
    #pragma unroll
    for (int p = 0; p < NP; p++) {
        float prev = h_s[tid + HALO + p * 128];
        #pragma unroll
        for (int o = 0; o < C_N; o++) {
            float gate = gb_s[o];
            #pragma unroll
            for (int c = 0; c < C_N; c++) gate = fmaf(gw_s[o][c], acc[c][p], gate);
            ob[(size_t)o * T_LEN + tile0 + tid + p * 128] =
                fast_tanh(acc[o][p]) * fast_sigmoid(gate) + prev;
        }
    }
}

// ---------------------------------------------------------------------------
// Layers 1..17: bf16 m16n8k16 mma.sync with tap-pairing + phase split.
// Tile = 256 output times = DIL phases x R rows (R = 256/DIL).
// SMEM A tiles: bf16 [phase][row][8ch], 16B per row; MMA A row m packs
// rows (base+m, base+m+1) = taps (2q+1, 2q).  3 terms: hihi + lohi + hilo.
// ---------------------------------------------------------------------------
template <int DIL>
__global__ void __launch_bounds__(128)
layer_mma(const float* __restrict__ h_in, float* __restrict__ h_out,
          const uint2* __restrict__ Bw,    // [2][25][32] uint2
          const float* __restrict__ bias, const float* __restrict__ gw,
          const float* __restrict__ gb) {
    constexpr int R = TILE_M / DIL;        // rows per phase
    constexpr int R16 = R / 16;            // m16 subtiles per phase
    constexpr int PHROWS = R + 49;         // rows per phase incl. halo
    constexpr int TROWS = TILE_M + 49 * DIL;
    constexpr int PARKPAD = 9;

    extern __shared__ __align__(16) char dyn[];
    __nv_bfloat16* h_hi = (__nv_bfloat16*)dyn;
    __nv_bfloat16* h_lo = h_hi + TROWS * 8;
    float* park = (float*)dyn;             // overlay after MMA passes
    __shared__ float ctrl[80];             // bias[8], gb[8], gw[64]

    const int b = blockIdx.y;
    const int tile0 = blockIdx.x * TILE_M;
    const int tid = threadIdx.x;
    const int wid = tid >> 5;
    const int lane = tid & 31;

    if (tid < 8) ctrl[tid] = bias[tid];
    else if (tid < 16) ctrl[tid] = gb[tid - 8];
    else if (tid < 80) ctrl[tid] = gw[tid - 16];

    // Stage hi/lo bf16 tiles, phase-major.
    const float* hb = h_in + (size_t)b * C_N * T_LEN;
    #pragma unroll
    for (int c = 0; c < C_N; c++) {
        const float* hc = hb + (size_t)c * T_LEN;
        for (int j = tid; j < TROWS; j += 128) {
            int t = tile0 - 49 * DIL + j;
            float v = (t >= 0) ? hc[t] : 0.0f;
            int row = j / DIL;
            int p = j % DIL;
            int idx = (p * PHROWS + row) * 8 + c;
            __nv_bfloat16 hi = __float2bfloat16_rn(v);
            h_hi[idx] = hi;
            h_lo[idx] = __float2bfloat16_rn(v - __bfloat162float(hi));
        }
    }
    __syncthreads();

    // Per-z ldmatrix base offsets (bytes within a tile).
    const int rowlane = (lane & 15) + (lane >> 4);
    u32 zb[4];
    #pragma unroll
    for (int z = 0; z < 4; z++) {
        int st = wid * 4 + z;
        int p = st / R16;
        int sub = st % R16;
        zb[z] = (u32)((p * PHROWS + sub * 16 + 48 + rowlane) * 16);
    }

    const u32 hi32 = smem_u32(h_hi);
    const u32 lo32 = smem_u32(h_lo);

    float acc[4][4];
    #pragma unroll
    for (int z = 0; z < 4; z++)
        #pragma unroll
        for (int q = 0; q < 4; q++) acc[z][q] = 0.0f;

    #pragma unroll 1
    for (int pass = 0; pass < 3; pass++) {
        const u32 ab = (pass == 1) ? lo32 : hi32;
        const uint2* bw = Bw + ((pass == 2) ? 800 : 0) + lane;
        #pragma unroll 1
        for (int q = 0; q < 25; q++) {
            uint2 bb = bw[q * 32];
            #pragma unroll
            for (int z = 0; z < 4; z++) {
                u32 a0, a1, a2, a3;
                ldmA(a0, a1, a2, a3, ab + zb[z] - (u32)(q * 32));
                mma16(acc[z], a0, a1, a2, a3, bb.x, bb.y);
            }
        }
    }

    // Park conv outputs to SMEM [time][9] fp32 (overlay on A tiles).
    __syncthreads();
    {
        const int g = lane >> 2;
        const int tig = lane & 3;
        #pragma unroll
        for (int z = 0; z < 4; z++) {
            int st = wid * 4 + z;
            int p = st / R16;
            int sub = st % R16;
            int i0 = (sub * 16 + g) * DIL + p;
            int i1 = i0 + 8 * DIL;
            park[i0 * PARKPAD + 2 * tig] = acc[z][0];
            park[i0 * PARKPAD + 2 * tig + 1] = acc[z][1];
            park[i1 * PARKPAD + 2 * tig] = acc[z][2];
            park[i1 * PARKPAD + 2 * tig + 1] = acc[z][3];
        }
    }
    __syncthreads();

    // Epilogue: rows tid and tid+128 (coalesced gmem).
    float* ob = h_out + (size_t)b * C_N * T_LEN;
    #pragma unroll
    for (int half = 0; half < 2; half++) {
        const int r = tid + half * 128;
        float outv[C_N];
        #pragma unroll
        for (int o = 0; o < C_N; o++) outv[o] = park[r * PARKPAD + o] + ctrl[o];
        #pragma unroll
        for (int o = 0; o < C_N; o++) {
            float gate = ctrl[8 + o];
            #pragma unroll
            for (int c = 0; c < C_N; c++)
                gate = fmaf(ctrl[16 + o * 8 + c], outv[c], gate);
            float prev = hb[(size_t)o * T_LEN + tile0 + r];
            ob[(size_t)o * T_LEN + tile0 + r] =
                fast_tanh(outv[o]) * fast_sigmoid(gate) + prev;
        }
    }
}

// ---------------------------------------------------------------------------
// Head
// ---------------------------------------------------------------------------
__global__ void __launch_bounds__(256)
head_kernel(const float* __restrict__ h,
            const float* __restrict__ mean_w, const float* __restrict__ mean_b,
            const float* __restrict__ lv_w, const float* __restrict__ lv_b,
            float* __restrict__ out) {
    const int b = blockIdx.y;
    const int t0 = (blockIdx.x * 256 + threadIdx.x) * 4;
    if (t0 >= T_LEN) return;
    const float* hbp = h + (size_t)b * C_N * T_LEN;
    float m[4], lv[4];
    float mb = mean_b[0], lb = lv_b[0];
    #pragma unroll
    for (int p = 0; p < 4; p++) { m[p] = mb; lv[p] = lb; }
    #pragma unroll
    for (int c = 0; c < C_N; c++) {
        float4 hv = *(const float4*)&hbp[(size_t)c * T_LEN + t0];
        float mw = mean_w[c], lw = lv_w[c];
        m[0] = fmaf(mw, hv.x, m[0]); lv[0] = fmaf(lw, hv.x, lv[0]);
        m[1] = fmaf(mw, hv.y, m[1]); lv[1] = fmaf(lw, hv.y, lv[1]);
        m[2] = fmaf(mw, hv.z, m[2]); lv[2] = fmaf(lw, hv.z, lv[2]);
        m[3] = fmaf(mw, hv.w, m[3]); lv[3] = fmaf(lw, hv.w, lv[3]);
    }
    float s[4];
    #pragma unroll
    for (int p = 0; p < 4; p++) s[p] = expf(0.5f * lv[p]);
    *(float4*)&out[(size_t)b * T_LEN + t0] = make_float4(m[0], m[1], m[2], m[3]);
    *(float4*)&out[(size_t)B_N * T_LEN + (size_t)b * T_LEN + t0] =
        make_float4(s[0], s[1], s[2], s[3]);
}

// ---------------------------------------------------------------------------
static int smem_for_dil(int d) {
    int trows = TILE_M + 49 * d;
    int tiles = 2 * trows * 16;            // hi + lo bf16 tiles
    int park = TILE_M * 9 * 4;
    return tiles > park ? tiles : park;
}

extern "C" void kernel_launch(void* const* d_in, const int* in_sizes, int n_in,
                              void* d_out, int out_size) {
    (void)in_sizes; (void)n_in; (void)out_size;
    const float* x      = (const float*)d_in[0];
    const float* v0     = (const float*)d_in[1];
    const float* g0     = (const float*)d_in[2];
    const float* b0     = (const float*)d_in[3];
    const float* gw0    = (const float*)d_in[4];
    const float* gb0    = (const float*)d_in[5];
    const float* vs     = (const float*)d_in[6];
    const float* gs     = (const float*)d_in[7];
    const float* bs     = (const float*)d_in[8];
    const float* gws    = (const float*)d_in[9];
    const float* gbs    = (const float*)d_in[10];
    const float* mean_w = (const float*)d_in[11];
    const float* mean_b = (const float*)d_in[12];
    const float* lv_w   = (const float*)d_in[13];
    const float* lv_b   = (const float*)d_in[14];

    float *bufA, *bufB;
    uint2* Bw;
    cudaGetSymbolAddress((void**)&bufA, g_h0);
    cudaGetSymbolAddress((void**)&bufB, g_h1);
    cudaGetSymbolAddress((void**)&Bw, g_Bw);

    cudaFuncSetAttribute(layer_mma<1>, cudaFuncAttributeMaxDynamicSharedMemorySize, smem_for_dil(1));
    cudaFuncSetAttribute(layer_mma<2>, cudaFuncAttributeMaxDynamicSharedMemorySize, smem_for_dil(2));
    cudaFuncSetAttribute(layer_mma<4>, cudaFuncAttributeMaxDynamicSharedMemorySize, smem_for_dil(4));
    cudaFuncSetAttribute(layer_mma<8>, cudaFuncAttributeMaxDynamicSharedMemorySize, smem_for_dil(8));

    prep_weights<<<dim3(18, 8), 128>>>(v0, g0, vs, gs);

    layer0_kernel<<<dim3(T_LEN / 512, B_N), 128>>>(x, bufA, b0, gw0, gb0);

    static const int dils[18] = {1,1,1,1,1,1,1,2,2,2,2,4,4,4,4,8,8,8};
    dim3 grid(T_LEN / TILE_M, B_N);
    float* cur = bufA;
    float* nxt = bufB;
    for (int i = 1; i < 18; i++) {
        const uint2* Wl  = Bw + (size_t)(i - 1) * 1600;
        const float* bl  = bs  + (i - 1) * C_N;
        const float* gwl = gws + (i - 1) * C_N * C_N;
        const float* gbl = gbs + (i - 1) * C_N;
        switch (dils[i]) {
            case 1: layer_mma<1><<<grid, 128, smem_for_dil(1)>>>(cur, nxt, Wl, bl, gwl, gbl); break;
            case 2: layer_mma<2><<<grid, 128, smem_for_dil(2)>>>(cur, nxt, Wl, bl, gwl, gbl); break;
            case 4: layer_mma<4><<<grid, 128, smem_for_dil(4)>>>(cur, nxt, Wl, bl, gwl, gbl); break;
            case 8: layer_mma<8><<<grid, 128, smem_for_dil(8)>>>(cur, nxt, Wl, bl, gwl, gbl); break;
        }
        float* t = cur; cur = nxt; nxt = t;
    }

    head_kernel<<<dim3(T_LEN / (256 * 4), B_N), 256>>>(
        cur, mean_w, mean_b, lv_w, lv_b, (float*)d_out);
}

// round 7
// speedup vs baseline: 1.8994x; 1.4457x over previous
#include <cuda_runtime.h>
#include <cuda_bf16.h>
#include <math.h>
#include <stdint.h>

typedef uint32_t u32;
typedef uint64_t u64;

#define T_LEN 262144
#define B_N 8
#define C_N 8
#define K_N 50
#define TILE_M 256

// Ping-pong hidden state [B][C][T]
__device__ float g_h0[B_N * C_N * T_LEN];
__device__ float g_h1[B_N * C_N * T_LEN];
// Layer-0 scalar weights [k][o]
__device__ float g_W0[K_N * C_N];
// Layers 1..17 B fragments: [layer][hl(hi,lo)][qpair(25)][lane(32)] uint2(b0,b1)
__device__ uint2 g_Bw[17 * 2 * 25 * 32];

// ---------------------------------------------------------------------------
__device__ __forceinline__ u32 smem_u32(const void* p) {
    return (u32)__cvta_generic_to_shared(p);
}
__device__ __forceinline__ void ldmA(u32& a0, u32& a1, u32& a2, u32& a3, u32 addr) {
    asm volatile("ldmatrix.sync.aligned.m8n8.x4.shared.b16 {%0,%1,%2,%3}, [%4];"
                 : "=r"(a0), "=r"(a1), "=r"(a2), "=r"(a3) : "r"(addr));
}
__device__ __forceinline__ void mma16(float* c, u32 a0, u32 a1, u32 a2, u32 a3,
                                      u32 b0, u32 b1) {
    asm volatile("mma.sync.aligned.m16n8k16.row.col.f32.bf16.bf16.f32 "
                 "{%0,%1,%2,%3},{%4,%5,%6,%7},{%8,%9},{%0,%1,%2,%3};"
                 : "+f"(c[0]), "+f"(c[1]), "+f"(c[2]), "+f"(c[3])
                 : "r"(a0), "r"(a1), "r"(a2), "r"(a3), "r"(b0), "r"(b1));
}
__device__ __forceinline__ u32 pack_bf16(float a, float b) {
    __nv_bfloat162 t = __floats2bfloat162_rn(a, b);
    return *(u32*)&t;
}
__device__ __forceinline__ float fast_tanh(float x) {
    x = fminf(fmaxf(x, -30.0f), 30.0f);
    float e = __expf(-2.0f * x);
    return (1.0f - e) / (1.0f + e);
}
__device__ __forceinline__ float fast_sigmoid(float x) {
    x = fminf(fmaxf(x, -30.0f), 30.0f);
    return 1.0f / (1.0f + __expf(-x));
}

// ---------------------------------------------------------------------------
// Weight prep: weight-norm; layer0 scalar weights + bf16 hi/lo tap-pair frags.
// ---------------------------------------------------------------------------
__global__ void prep_weights(const float* __restrict__ v0,
                             const float* __restrict__ g0,
                             const float* __restrict__ vs,
                             const float* __restrict__ gs) {
    int l = blockIdx.x;   // 0..17
    int o = blockIdx.y;   // 0..7
    int cin = (l == 0) ? 1 : C_N;
    const float* v;
    float g;
    if (l == 0) {
        v = v0 + o * K_N;
        g = g0[o];
    } else {
        v = vs + (size_t)((l - 1) * C_N + o) * C_N * K_N;
        g = gs[(l - 1) * C_N + o];
    }
    int n = cin * K_N;
    float s = 0.0f;
    for (int i = threadIdx.x; i < n; i += blockDim.x) {
        float x = v[i];
        s += x * x;
    }
    __shared__ float red[4];
    #pragma unroll
    for (int off = 16; off > 0; off >>= 1)
        s += __shfl_down_sync(0xffffffffu, s, off);
    if ((threadIdx.x & 31) == 0) red[threadIdx.x >> 5] = s;
    __syncthreads();
    float scale = g * rsqrtf(red[0] + red[1] + red[2] + red[3]);

    if (l == 0) {
        for (int i = threadIdx.x; i < n; i += blockDim.x)
            g_W0[i * C_N + o] = scale * v[i];   // i == k
    } else {
        int tid = threadIdx.x;
        if (tid < 100) {
            int q = tid >> 2;
            int tig = tid & 3;
            int k1 = 48 - 2 * q;   // b0 tap
            int k2 = 49 - 2 * q;   // b1 tap
            float wa = scale * v[(2 * tig) * K_N + k1];
            float wb = scale * v[(2 * tig + 1) * K_N + k1];
            float wc = scale * v[(2 * tig) * K_N + k2];
            float wd = scale * v[(2 * tig + 1) * K_N + k2];
            float ha = __bfloat162float(__float2bfloat16_rn(wa));
            float hb = __bfloat162float(__float2bfloat16_rn(wb));
            float hc = __bfloat162float(__float2bfloat16_rn(wc));
            float hd = __bfloat162float(__float2bfloat16_rn(wd));
            size_t base = (size_t)(l - 1) * 1600 + q * 32 + o * 4 + tig;
            g_Bw[base] = make_uint2(pack_bf16(wa, wb), pack_bf16(wc, wd));          // hi
            g_Bw[base + 800] = make_uint2(pack_bf16(wa - ha, wb - hb),
                                          pack_bf16(wc - hc, wd - hd));             // lo
        }
    }
}

// ---------------------------------------------------------------------------
// Layer 0 (scalar; C_in = 1, dilation 1)
// ---------------------------------------------------------------------------
__global__ void __launch_bounds__(128)
layer0_kernel(const float* __restrict__ h_in, float* __restrict__ h_out,
              const float* __restrict__ bias, const float* __restrict__ gw,
              const float* __restrict__ gb) {
    constexpr int NP = 4;
    constexpr int TILE = 128 * NP;
    constexpr int HALO = K_N - 1;
    constexpr int HW = TILE + HALO;

    __shared__ __align__(16) float h_s[HW];
    __shared__ __align__(16) float w_s[K_N][C_N];
    __shared__ float gw_s[C_N][C_N];
    __shared__ float b_s[C_N];
    __shared__ float gb_s[C_N];

    const int b = blockIdx.y;
    const int tile0 = blockIdx.x * TILE;
    const int tid = threadIdx.x;

    for (int i = tid; i < K_N * C_N; i += 128) (&w_s[0][0])[i] = g_W0[i];
    for (int i = tid; i < C_N * C_N; i += 128) (&gw_s[0][0])[i] = gw[i];
    if (tid < C_N) { b_s[tid] = bias[tid]; gb_s[tid] = gb[tid]; }

    const float* hb = h_in + (size_t)b * T_LEN;
    for (int j = tid; j < HW; j += 128) {
        int t = tile0 - HALO + j;
        h_s[j] = (t >= 0) ? hb[t] : 0.0f;
    }
    __syncthreads();

    float acc[C_N][NP];
    #pragma unroll
    for (int o = 0; o < C_N; o++) {
        float bv = b_s[o];
        #pragma unroll
        for (int p = 0; p < NP; p++) acc[o][p] = bv;
    }

    #pragma unroll 1
    for (int k = 0; k < K_N; k++) {
        float hv[NP];
        #pragma unroll
        for (int p = 0; p < NP; p++) hv[p] = h_s[tid + k + p * 128];
        float wv[C_N];
        *(float4*)&wv[0] = *(const float4*)&w_s[k][0];
        *(float4*)&wv[4] = *(const float4*)&w_s[k][4];
        #pragma unroll
        for (int o = 0; o < C_N; o++)
            #pragma unroll
            for (int p = 0; p < NP; p++)
                acc[o][p] = fmaf(wv[o], hv[p], acc[o][p]);
    }

    float* ob = h_out + (size_t)b * C_N * T_LEN;
    #pragma unroll
    for (int p = 0; p < NP; p++) {
        float prev = h_s[tid + HALO + p * 128];
        #pragma unroll
        for (int o = 0; o < C_N; o++) {
            float gate = gb_s[o];
            #pragma unroll
            for (int c = 0; c < C_N; c++) gate = fmaf(gw_s[o][c], acc[c][p], gate);
            ob[(size_t)o * T_LEN + tile0 + tid + p * 128] =
                fast_tanh(acc[o][p]) * fast_sigmoid(gate) + prev;
        }
    }
}

// ---------------------------------------------------------------------------
// Layers 1..17: bf16 m16n8k16 mma.sync with tap-pairing + phase split.
// Register-capped (6 blocks/SM) + prefetched/unrolled q-loop for latency.
// ---------------------------------------------------------------------------
template <int DIL>
__global__ void __launch_bounds__(128, 6)
layer_mma(const float* __restrict__ h_in, float* __restrict__ h_out,
          const uint2* __restrict__ Bw,    // [2][25][32] uint2
          const float* __restrict__ bias, const float* __restrict__ gw,
          const float* __restrict__ gb) {
    constexpr int R = TILE_M / DIL;        // rows per phase
    constexpr int R16 = R / 16;            // m16 subtiles per phase
    constexpr int PHROWS = R + 49;         // rows per phase incl. halo
    constexpr int TROWS = TILE_M + 49 * DIL;
    constexpr int PARKPAD = 9;

    extern __shared__ __align__(16) char dyn[];
    __nv_bfloat16* h_hi = (__nv_bfloat16*)dyn;
    __nv_bfloat16* h_lo = h_hi + TROWS * 8;
    float* park = (float*)dyn;             // overlay after MMA passes
    __shared__ float ctrl[80];             // bias[8], gb[8], gw[64]

    const int b = blockIdx.y;
    const int tile0 = blockIdx.x * TILE_M;
    const int tid = threadIdx.x;
    const int wid = tid >> 5;
    const int lane = tid & 31;

    if (tid < 8) ctrl[tid] = bias[tid];
    else if (tid < 16) ctrl[tid] = gb[tid - 8];
    else if (tid < 80) ctrl[tid] = gw[tid - 16];

    // Stage hi/lo bf16 tiles, phase-major.
    const float* hb = h_in + (size_t)b * C_N * T_LEN;
    #pragma unroll
    for (int c = 0; c < C_N; c++) {
        const float* hc = hb + (size_t)c * T_LEN;
        for (int j = tid; j < TROWS; j += 128) {
            int t = tile0 - 49 * DIL + j;
            float v = (t >= 0) ? hc[t] : 0.0f;
            int row = j / DIL;
            int p = j % DIL;
            int idx = (p * PHROWS + row) * 8 + c;
            __nv_bfloat16 hi = __float2bfloat16_rn(v);
            h_hi[idx] = hi;
            h_lo[idx] = __float2bfloat16_rn(v - __bfloat162float(hi));
        }
    }
    __syncthreads();

    // Per-z ldmatrix base offsets (bytes within a tile).
    const int rowlane = (lane & 15) + (lane >> 4);
    u32 zb[4];
    #pragma unroll
    for (int z = 0; z < 4; z++) {
        int st = wid * 4 + z;
        int p = st / R16;
        int sub = st % R16;
        zb[z] = (u32)((p * PHROWS + sub * 16 + 48 + rowlane) * 16);
    }

    const u32 hi32 = smem_u32(h_hi);
    const u32 lo32 = smem_u32(h_lo);

    float acc[4][4];
    #pragma unroll
    for (int z = 0; z < 4; z++)
        #pragma unroll
        for (int q = 0; q < 4; q++) acc[z][q] = 0.0f;

    #pragma unroll 1
    for (int pass = 0; pass < 3; pass++) {
        const u32 ab = (pass == 1) ? lo32 : hi32;
        const uint2* bw = Bw + ((pass == 2) ? 800 : 0) + lane;
        uint2 bb = *bw;                       // prefetch q=0
        #pragma unroll 5
        for (int q = 0; q < 25; q++) {
            uint2 nb = (q < 24) ? bw[(q + 1) * 32] : bb;   // prefetch next
            u32 base = ab - (u32)(q * 32);
            #pragma unroll
            for (int z = 0; z < 4; z++) {
                u32 a0, a1, a2, a3;
                ldmA(a0, a1, a2, a3, base + zb[z]);
                mma16(acc[z], a0, a1, a2, a3, bb.x, bb.y);
            }
            bb = nb;
        }
    }

    // Park conv outputs to SMEM [time][9] fp32 (overlay on A tiles).
    __syncthreads();
    {
        const int g = lane >> 2;
        const int tig = lane & 3;
        #pragma unroll
        for (int z = 0; z < 4; z++) {
            int st = wid * 4 + z;
            int p = st / R16;
            int sub = st % R16;
            int i0 = (sub * 16 + g) * DIL + p;
            int i1 = i0 + 8 * DIL;
            park[i0 * PARKPAD + 2 * tig] = acc[z][0];
            park[i0 * PARKPAD + 2 * tig + 1] = acc[z][1];
            park[i1 * PARKPAD + 2 * tig] = acc[z][2];
            park[i1 * PARKPAD + 2 * tig + 1] = acc[z][3];
        }
    }
    __syncthreads();

    // Epilogue: rows tid and tid+128 (coalesced gmem).
    float* ob = h_out + (size_t)b * C_N * T_LEN;
    #pragma unroll
    for (int half = 0; half < 2; half++) {
        const int r = tid + half * 128;
        float outv[C_N];
        #pragma unroll
        for (int o = 0; o < C_N; o++) outv[o] = park[r * PARKPAD + o] + ctrl[o];
        #pragma unroll
        for (int o = 0; o < C_N; o++) {
            float gate = ctrl[8 + o];
            #pragma unroll
            for (int c = 0; c < C_N; c++)
                gate = fmaf(ctrl[16 + o * 8 + c], outv[c], gate);
            float prev = hb[(size_t)o * T_LEN + tile0 + r];
            ob[(size_t)o * T_LEN + tile0 + r] =
                fast_tanh(outv[o]) * fast_sigmoid(gate) + prev;
        }
    }
}

// ---------------------------------------------------------------------------
// Head
// ---------------------------------------------------------------------------
__global__ void __launch_bounds__(256)
head_kernel(const float* __restrict__ h,
            const float* __restrict__ mean_w, const float* __restrict__ mean_b,
            const float* __restrict__ lv_w, const float* __restrict__ lv_b,
            float* __restrict__ out) {
    const int b = blockIdx.y;
    const int t0 = (blockIdx.x * 256 + threadIdx.x) * 4;
    if (t0 >= T_LEN) return;
    const float* hbp = h + (size_t)b * C_N * T_LEN;
    float m[4], lv[4];
    float mb = mean_b[0], lb = lv_b[0];
    #pragma unroll
    for (int p = 0; p < 4; p++) { m[p] = mb; lv[p] = lb; }
    #pragma unroll
    for (int c = 0; c < C_N; c++) {
        float4 hv = *(const float4*)&hbp[(size_t)c * T_LEN + t0];
        float mw = mean_w[c], lw = lv_w[c];
        m[0] = fmaf(mw, hv.x, m[0]); lv[0] = fmaf(lw, hv.x, lv[0]);
        m[1] = fmaf(mw, hv.y, m[1]); lv[1] = fmaf(lw, hv.y, lv[1]);
        m[2] = fmaf(mw, hv.z, m[2]); lv[2] = fmaf(lw, hv.z, lv[2]);
        m[3] = fmaf(mw, hv.w, m[3]); lv[3] = fmaf(lw, hv.w, lv[3]);
    }
    float s[4];
    #pragma unroll
    for (int p = 0; p < 4; p++) s[p] = expf(0.5f * lv[p]);
    *(float4*)&out[(size_t)b * T_LEN + t0] = make_float4(m[0], m[1], m[2], m[3]);
    *(float4*)&out[(size_t)B_N * T_LEN + (size_t)b * T_LEN + t0] =
        make_float4(s[0], s[1], s[2], s[3]);
}

// ---------------------------------------------------------------------------
static int smem_for_dil(int d) {
    int trows = TILE_M + 49 * d;
    int tiles = 2 * trows * 16;            // hi + lo bf16 tiles
    int park = TILE_M * 9 * 4;
    return tiles > park ? tiles : park;
}

extern "C" void kernel_launch(void* const* d_in, const int* in_sizes, int n_in,
                              void* d_out, int out_size) {
    (void)in_sizes; (void)n_in; (void)out_size;
    const float* x      = (const float*)d_in[0];
    const float* v0     = (const float*)d_in[1];
    const float* g0     = (const float*)d_in[2];
    const float* b0     = (const float*)d_in[3];
    const float* gw0    = (const float*)d_in[4];
    const float* gb0    = (const float*)d_in[5];
    const float* vs     = (const float*)d_in[6];
    const float* gs     = (const float*)d_in[7];
    const float* bs     = (const float*)d_in[8];
    const float* gws    = (const float*)d_in[9];
    const float* gbs    = (const float*)d_in[10];
    const float* mean_w = (const float*)d_in[11];
    const float* mean_b = (const float*)d_in[12];
    const float* lv_w   = (const float*)d_in[13];
    const float* lv_b   = (const float*)d_in[14];

    float *bufA, *bufB;
    uint2* Bw;
    cudaGetSymbolAddress((void**)&bufA, g_h0);
    cudaGetSymbolAddress((void**)&bufB, g_h1);
    cudaGetSymbolAddress((void**)&Bw, g_Bw);

    cudaFuncSetAttribute(layer_mma<1>, cudaFuncAttributeMaxDynamicSharedMemorySize, smem_for_dil(1));
    cudaFuncSetAttribute(layer_mma<2>, cudaFuncAttributeMaxDynamicSharedMemorySize, smem_for_dil(2));
    cudaFuncSetAttribute(layer_mma<4>, cudaFuncAttributeMaxDynamicSharedMemorySize, smem_for_dil(4));
    cudaFuncSetAttribute(layer_mma<8>, cudaFuncAttributeMaxDynamicSharedMemorySize, smem_for_dil(8));

    prep_weights<<<dim3(18, 8), 128>>>(v0, g0, vs, gs);

    layer0_kernel<<<dim3(T_LEN / 512, B_N), 128>>>(x, bufA, b0, gw0, gb0);

    static const int dils[18] = {1,1,1,1,1,1,1,2,2,2,2,4,4,4,4,8,8,8};
    dim3 grid(T_LEN / TILE_M, B_N);
    float* cur = bufA;
    float* nxt = bufB;
    for (int i = 1; i < 18; i++) {
        const uint2* Wl  = Bw + (size_t)(i - 1) * 1600;
        const float* bl  = bs  + (i - 1) * C_N;
        const float* gwl = gws + (i - 1) * C_N * C_N;
        const float* gbl = gbs + (i - 1) * C_N;
        switch (dils[i]) {
            case 1: layer_mma<1><<<grid, 128, smem_for_dil(1)>>>(cur, nxt, Wl, bl, gwl, gbl); break;
            case 2: layer_mma<2><<<grid, 128, smem_for_dil(2)>>>(cur, nxt, Wl, bl, gwl, gbl); break;
            case 4: layer_mma<4><<<grid, 128, smem_for_dil(4)>>>(cur, nxt, Wl, bl, gwl, gbl); break;
            case 8: layer_mma<8><<<grid, 128, smem_for_dil(8)>>>(cur, nxt, Wl, bl, gwl, gbl); break;
        }
        float* t = cur; cur = nxt; nxt = t;
    }

    head_kernel<<<dim3(T_LEN / (256 * 4), B_N), 256>>>(
        cur, mean_w, mean_b, lv_w, lv_b, (float*)d_out);
}

// round 8
// speedup vs baseline: 3.2960x; 1.7353x over previous
#include <cuda_runtime.h>
#include <cuda_bf16.h>
#include <math.h>
#include <stdint.h>

typedef uint32_t u32;
typedef uint64_t u64;

#define T_LEN 262144
#define B_N 8
#define C_N 8
#define K_N 50
#define TILE_M 256

// Ping-pong hidden state [B][C][T]
__device__ float g_h0[B_N * C_N * T_LEN];
__device__ float g_h1[B_N * C_N * T_LEN];
// Layer-0 scalar weights [k][o]
__device__ float g_W0[K_N * C_N];
// Layers 1..17 B fragments: [layer][hl(hi,lo)][qpair(25)][lane(32)] uint2(b0,b1)
__device__ uint2 g_Bw[17 * 2 * 25 * 32];

// ---------------------------------------------------------------------------
__device__ __forceinline__ u32 smem_u32(const void* p) {
    return (u32)__cvta_generic_to_shared(p);
}
__device__ __forceinline__ void ldmA(u32& a0, u32& a1, u32& a2, u32& a3, u32 addr) {
    asm volatile("ldmatrix.sync.aligned.m8n8.x4.shared.b16 {%0,%1,%2,%3}, [%4];"
                 : "=r"(a0), "=r"(a1), "=r"(a2), "=r"(a3) : "r"(addr));
}
__device__ __forceinline__ void mma16(float* c, u32 a0, u32 a1, u32 a2, u32 a3,
                                      u32 b0, u32 b1) {
    asm volatile("mma.sync.aligned.m16n8k16.row.col.f32.bf16.bf16.f32 "
                 "{%0,%1,%2,%3},{%4,%5,%6,%7},{%8,%9},{%0,%1,%2,%3};"
                 : "+f"(c[0]), "+f"(c[1]), "+f"(c[2]), "+f"(c[3])
                 : "r"(a0), "r"(a1), "r"(a2), "r"(a3), "r"(b0), "r"(b1));
}
__device__ __forceinline__ u32 pack_bf16(float a, float b) {
    __nv_bfloat162 t = __floats2bfloat162_rn(a, b);
    return *(u32*)&t;
}
__device__ __forceinline__ float fast_tanh(float x) {
    x = fminf(fmaxf(x, -30.0f), 30.0f);
    float e = __expf(-2.0f * x);
    return (1.0f - e) / (1.0f + e);
}
__device__ __forceinline__ float fast_sigmoid(float x) {
    x = fminf(fmaxf(x, -30.0f), 30.0f);
    return 1.0f / (1.0f + __expf(-x));
}

// ---------------------------------------------------------------------------
// Weight prep: weight-norm; layer0 scalar weights + bf16 hi/lo tap-pair frags.
// ---------------------------------------------------------------------------
__global__ void prep_weights(const float* __restrict__ v0,
                             const float* __restrict__ g0,
                             const float* __restrict__ vs,
                             const float* __restrict__ gs) {
    int l = blockIdx.x;   // 0..17
    int o = blockIdx.y;   // 0..7
    int cin = (l == 0) ? 1 : C_N;
    const float* v;
    float g;
    if (l == 0) {
        v = v0 + o * K_N;
        g = g0[o];
    } else {
        v = vs + (size_t)((l - 1) * C_N + o) * C_N * K_N;
        g = gs[(l - 1) * C_N + o];
    }
    int n = cin * K_N;
    float s = 0.0f;
    for (int i = threadIdx.x; i < n; i += blockDim.x) {
        float x = v[i];
        s += x * x;
    }
    __shared__ float red[4];
    #pragma unroll
    for (int off = 16; off > 0; off >>= 1)
        s += __shfl_down_sync(0xffffffffu, s, off);
    if ((threadIdx.x & 31) == 0) red[threadIdx.x >> 5] = s;
    __syncthreads();
    float scale = g * rsqrtf(red[0] + red[1] + red[2] + red[3]);

    if (l == 0) {
        for (int i = threadIdx.x; i < n; i += blockDim.x)
            g_W0[i * C_N + o] = scale * v[i];   // i == k
    } else {
        int tid = threadIdx.x;
        if (tid < 100) {
            int q = tid >> 2;
            int tig = tid & 3;
            int k1 = 48 - 2 * q;   // b0 tap
            int k2 = 49 - 2 * q;   // b1 tap
            float wa = scale * v[(2 * tig) * K_N + k1];
            float wb = scale * v[(2 * tig + 1) * K_N + k1];
            float wc = scale * v[(2 * tig) * K_N + k2];
            float wd = scale * v[(2 * tig + 1) * K_N + k2];
            float ha = __bfloat162float(__float2bfloat16_rn(wa));
            float hb = __bfloat162float(__float2bfloat16_rn(wb));
            float hc = __bfloat162float(__float2bfloat16_rn(wc));
            float hd = __bfloat162float(__float2bfloat16_rn(wd));
            size_t base = (size_t)(l - 1) * 1600 + q * 32 + o * 4 + tig;
            g_Bw[base] = make_uint2(pack_bf16(wa, wb), pack_bf16(wc, wd));          // hi
            g_Bw[base + 800] = make_uint2(pack_bf16(wa - ha, wb - hb),
                                          pack_bf16(wc - hc, wd - hd));             // lo
        }
    }
}

// ---------------------------------------------------------------------------
// Layer 0 (scalar; C_in = 1, dilation 1)
// ---------------------------------------------------------------------------
__global__ void __launch_bounds__(128)
layer0_kernel(const float* __restrict__ h_in, float* __restrict__ h_out,
              const float* __restrict__ bias, const float* __restrict__ gw,
              const float* __restrict__ gb) {
    constexpr int NP = 4;
    constexpr int TILE = 128 * NP;
    constexpr int HALO = K_N - 1;
    constexpr int HW = TILE + HALO;

    __shared__ __align__(16) float h_s[HW];
    __shared__ __align__(16) float w_s[K_N][C_N];
    __shared__ float gw_s[C_N][C_N];
    __shared__ float b_s[C_N];
    __shared__ float gb_s[C_N];

    const int b = blockIdx.y;
    const int tile0 = blockIdx.x * TILE;
    const int tid = threadIdx.x;

    for (int i = tid; i < K_N * C_N; i += 128) (&w_s[0][0])[i] = g_W0[i];
    for (int i = tid; i < C_N * C_N; i += 128) (&gw_s[0][0])[i] = gw[i];
    if (tid < C_N) { b_s[tid] = bias[tid]; gb_s[tid] = gb[tid]; }

    const float* hb = h_in + (size_t)b * T_LEN;
    for (int j = tid; j < HW; j += 128) {
        int t = tile0 - HALO + j;
        h_s[j] = (t >= 0) ? hb[t] : 0.0f;
    }
    __syncthreads();

    float acc[C_N][NP];
    #pragma unroll
    for (int o = 0; o < C_N; o++) {
        float bv = b_s[o];
        #pragma unroll
        for (int p = 0; p < NP; p++) acc[o][p] = bv;
    }

    #pragma unroll 1
    for (int k = 0; k < K_N; k++) {
        float hv[NP];
        #pragma unroll
        for (int p = 0; p < NP; p++) hv[p] = h_s[tid + k + p * 128];
        float wv[C_N];
        *(float4*)&wv[0] = *(const float4*)&w_s[k][0];
        *(float4*)&wv[4] = *(const float4*)&w_s[k][4];
        #pragma unroll
        for (int o = 0; o < C_N; o++)
            #pragma unroll
            for (int p = 0; p < NP; p++)
                acc[o][p] = fmaf(wv[o], hv[p], acc[o][p]);
    }

    float* ob = h_out + (size_t)b * C_N * T_LEN;
    #pragma unroll
    for (int p = 0; p < NP; p++) {
        float prev = h_s[tid + HALO + p * 128];
        #pragma unroll
        for (int o = 0; o < C_N; o++) {
            float gate = gb_s[o];
            #pragma unroll
            for (int c = 0; c < C_N; c++) gate = fmaf(gw_s[o][c], acc[c][p], gate);
            ob[(size_t)o * T_LEN + tile0 + tid + p * 128] =
                fast_tanh(acc[o][p]) * fast_sigmoid(gate) + prev;
        }
    }
}

// ---------------------------------------------------------------------------
// Layers 1..17: bf16 m16n8k16 mma.sync with tap-pairing + phase split.
// Fused hi/lo passes: per (q,z) load Ahi+Alo once, 3 MMAs into one acc.
// Staging via per-row STS.128 (conflict-free).
// ---------------------------------------------------------------------------
template <int DIL>
__global__ void __launch_bounds__(128, 6)
layer_mma(const float* __restrict__ h_in, float* __restrict__ h_out,
          const uint2* __restrict__ Bw,    // [2][25][32] uint2
          const float* __restrict__ bias, const float* __restrict__ gw,
          const float* __restrict__ gb) {
    constexpr int R = TILE_M / DIL;        // rows per phase
    constexpr int R16 = R / 16;            // m16 subtiles per phase
    constexpr int PHROWS = R + 49;         // rows per phase incl. halo
    constexpr int TROWS = TILE_M + 49 * DIL;
    constexpr int PARKPAD = 9;

    extern __shared__ __align__(16) char dyn[];
    __nv_bfloat16* h_hi = (__nv_bfloat16*)dyn;
    __nv_bfloat16* h_lo = h_hi + TROWS * 8;
    float* park = (float*)dyn;             // overlay after MMA passes
    __shared__ float ctrl[80];             // bias[8], gb[8], gw[64]

    const int b = blockIdx.y;
    const int tile0 = blockIdx.x * TILE_M;
    const int tid = threadIdx.x;
    const int wid = tid >> 5;
    const int lane = tid & 31;

    if (tid < 8) ctrl[tid] = bias[tid];
    else if (tid < 16) ctrl[tid] = gb[tid - 8];
    else if (tid < 80) ctrl[tid] = gw[tid - 16];

    // Stage hi/lo bf16 tiles, phase-major.  One thread per time-row:
    // gather 8 channels (coalesced per channel), pack, STS.128 (no conflicts).
    const float* hb = h_in + (size_t)b * C_N * T_LEN;
    for (int j = tid; j < TROWS; j += 128) {
        int t = tile0 - 49 * DIL + j;
        float v[C_N];
        #pragma unroll
        for (int c = 0; c < C_N; c++)
            v[c] = (t >= 0) ? hb[(size_t)c * T_LEN + t] : 0.0f;
        u32 hw[4], lw[4];
        #pragma unroll
        for (int i = 0; i < 4; i++) {
            float a = v[2 * i], bb2 = v[2 * i + 1];
            float ah = __bfloat162float(__float2bfloat16_rn(a));
            float bh = __bfloat162float(__float2bfloat16_rn(bb2));
            hw[i] = pack_bf16(a, bb2);
            lw[i] = pack_bf16(a - ah, bb2 - bh);
        }
        int row = j / DIL;
        int p = j % DIL;
        int idx = (p * PHROWS + row) * 8;
        *(uint4*)&h_hi[idx] = make_uint4(hw[0], hw[1], hw[2], hw[3]);
        *(uint4*)&h_lo[idx] = make_uint4(lw[0], lw[1], lw[2], lw[3]);
    }
    __syncthreads();

    // Per-z ldmatrix base offsets (bytes within a tile).
    const int rowlane = (lane & 15) + (lane >> 4);
    u32 zb[4];
    #pragma unroll
    for (int z = 0; z < 4; z++) {
        int st = wid * 4 + z;
        int p = st / R16;
        int sub = st % R16;
        zb[z] = (u32)((p * PHROWS + sub * 16 + 48 + rowlane) * 16);
    }

    const u32 hi32 = smem_u32(h_hi);
    const u32 lo32 = smem_u32(h_lo);

    float acc[4][4];
    #pragma unroll
    for (int z = 0; z < 4; z++)
        #pragma unroll
        for (int q = 0; q < 4; q++) acc[z][q] = 0.0f;

    {
        const uint2* bwhi = Bw + lane;
        const uint2* bwlo = Bw + 800 + lane;
        uint2 bh = *bwhi;                    // prefetch q=0
        uint2 bl = *bwlo;
        #pragma unroll 5
        for (int q = 0; q < 25; q++) {
            uint2 nh = (q < 24) ? bwhi[(q + 1) * 32] : bh;
            uint2 nl = (q < 24) ? bwlo[(q + 1) * 32] : bl;
            u32 off = (u32)(q * 32);
            #pragma unroll
            for (int z = 0; z < 4; z++) {
                u32 h0, h1, h2, h3, l0, l1, l2, l3;
                ldmA(h0, h1, h2, h3, hi32 + zb[z] - off);
                ldmA(l0, l1, l2, l3, lo32 + zb[z] - off);
                mma16(acc[z], h0, h1, h2, h3, bh.x, bh.y);
                mma16(acc[z], l0, l1, l2, l3, bh.x, bh.y);
                mma16(acc[z], h0, h1, h2, h3, bl.x, bl.y);
            }
            bh = nh;
            bl = nl;
        }
    }

    // Park conv outputs to SMEM [time][9] fp32 (overlay on A tiles).
    __syncthreads();
    {
        const int g = lane >> 2;
        const int tig = lane & 3;
        #pragma unroll
        for (int z = 0; z < 4; z++) {
            int st = wid * 4 + z;
            int p = st / R16;
            int sub = st % R16;
            int i0 = (sub * 16 + g) * DIL + p;
            int i1 = i0 + 8 * DIL;
            park[i0 * PARKPAD + 2 * tig] = acc[z][0];
            park[i0 * PARKPAD + 2 * tig + 1] = acc[z][1];
            park[i1 * PARKPAD + 2 * tig] = acc[z][2];
            park[i1 * PARKPAD + 2 * tig + 1] = acc[z][3];
        }
    }
    __syncthreads();

    // Epilogue: rows tid and tid+128 (coalesced gmem).
    float* ob = h_out + (size_t)b * C_N * T_LEN;
    #pragma unroll
    for (int half = 0; half < 2; half++) {
        const int r = tid + half * 128;
        float outv[C_N];
        #pragma unroll
        for (int o = 0; o < C_N; o++) outv[o] = park[r * PARKPAD + o] + ctrl[o];
        #pragma unroll
        for (int o = 0; o < C_N; o++) {
            float gate = ctrl[8 + o];
            #pragma unroll
            for (int c = 0; c < C_N; c++)
                gate = fmaf(ctrl[16 + o * 8 + c], outv[c], gate);
            float prev = hb[(size_t)o * T_LEN + tile0 + r];
            ob[(size_t)o * T_LEN + tile0 + r] =
                fast_tanh(outv[o]) * fast_sigmoid(gate) + prev;
        }
    }
}

// ---------------------------------------------------------------------------
// Head
// ---------------------------------------------------------------------------
__global__ void __launch_bounds__(256)
head_kernel(const float* __restrict__ h,
            const float* __restrict__ mean_w, const float* __restrict__ mean_b,
            const float* __restrict__ lv_w, const float* __restrict__ lv_b,
            float* __restrict__ out) {
    const int b = blockIdx.y;
    const int t0 = (blockIdx.x * 256 + threadIdx.x) * 4;
    if (t0 >= T_LEN) return;
    const float* hbp = h + (size_t)b * C_N * T_LEN;
    float m[4], lv[4];
    float mb = mean_b[0], lb = lv_b[0];
    #pragma unroll
    for (int p = 0; p < 4; p++) { m[p] = mb; lv[p] = lb; }
    #pragma unroll
    for (int c = 0; c < C_N; c++) {
        float4 hv = *(const float4*)&hbp[(size_t)c * T_LEN + t0];
        float mw = mean_w[c], lw = lv_w[c];
        m[0] = fmaf(mw, hv.x, m[0]); lv[0] = fmaf(lw, hv.x, lv[0]);
        m[1] = fmaf(mw, hv.y, m[1]); lv[1] = fmaf(lw, hv.y, lv[1]);
        m[2] = fmaf(mw, hv.z, m[2]); lv[2] = fmaf(lw, hv.z, lv[2]);
        m[3] = fmaf(mw, hv.w, m[3]); lv[3] = fmaf(lw, hv.w, lv[3]);
    }
    float s[4];
    #pragma unroll
    for (int p = 0; p < 4; p++) s[p] = expf(0.5f * lv[p]);
    *(float4*)&out[(size_t)b * T_LEN + t0] = make_float4(m[0], m[1], m[2], m[3]);
    *(float4*)&out[(size_t)B_N * T_LEN + (size_t)b * T_LEN + t0] =
        make_float4(s[0], s[1], s[2], s[3]);
}

// ---------------------------------------------------------------------------
static int smem_for_dil(int d) {
    int trows = TILE_M + 49 * d;
    int tiles = 2 * trows * 16;            // hi + lo bf16 tiles
    int park = TILE_M * 9 * 4;
    return tiles > park ? tiles : park;
}

extern "C" void kernel_launch(void* const* d_in, const int* in_sizes, int n_in,
                              void* d_out, int out_size) {
    (void)in_sizes; (void)n_in; (void)out_size;
    const float* x      = (const float*)d_in[0];
    const float* v0     = (const float*)d_in[1];
    const float* g0     = (const float*)d_in[2];
    const float* b0     = (const float*)d_in[3];
    const float* gw0    = (const float*)d_in[4];
    const float* gb0    = (const float*)d_in[5];
    const float* vs     = (const float*)d_in[6];
    const float* gs     = (const float*)d_in[7];
    const float* bs     = (const float*)d_in[8];
    const float* gws    = (const float*)d_in[9];
    const float* gbs    = (const float*)d_in[10];
    const float* mean_w = (const float*)d_in[11];
    const float* mean_b = (const float*)d_in[12];
    const float* lv_w   = (const float*)d_in[13];
    const float* lv_b   = (const float*)d_in[14];

    float *bufA, *bufB;
    uint2* Bw;
    cudaGetSymbolAddress((void**)&bufA, g_h0);
    cudaGetSymbolAddress((void**)&bufB, g_h1);
    cudaGetSymbolAddress((void**)&Bw, g_Bw);

    cudaFuncSetAttribute(layer_mma<1>, cudaFuncAttributeMaxDynamicSharedMemorySize, smem_for_dil(1));
    cudaFuncSetAttribute(layer_mma<2>, cudaFuncAttributeMaxDynamicSharedMemorySize, smem_for_dil(2));
    cudaFuncSetAttribute(layer_mma<4>, cudaFuncAttributeMaxDynamicSharedMemorySize, smem_for_dil(4));
    cudaFuncSetAttribute(layer_mma<8>, cudaFuncAttributeMaxDynamicSharedMemorySize, smem_for_dil(8));

    prep_weights<<<dim3(18, 8), 128>>>(v0, g0, vs, gs);

    layer0_kernel<<<dim3(T_LEN / 512, B_N), 128>>>(x, bufA, b0, gw0, gb0);

    static const int dils[18] = {1,1,1,1,1,1,1,2,2,2,2,4,4,4,4,8,8,8};
    dim3 grid(T_LEN / TILE_M, B_N);
    float* cur = bufA;
    float* nxt = bufB;
    for (int i = 1; i < 18; i++) {
        const uint2* Wl  = Bw + (size_t)(i - 1) * 1600;
        const float* bl  = bs  + (i - 1) * C_N;
        const float* gwl = gws + (i - 1) * C_N * C_N;
        const float* gbl = gbs + (i - 1) * C_N;
        switch (dils[i]) {
            case 1: layer_mma<1><<<grid, 128, smem_for_dil(1)>>>(cur, nxt, Wl, bl, gwl, gbl); break;
            case 2: layer_mma<2><<<grid, 128, smem_for_dil(2)>>>(cur, nxt, Wl, bl, gwl, gbl); break;
            case 4: layer_mma<4><<<grid, 128, smem_for_dil(4)>>>(cur, nxt, Wl, bl, gwl, gbl); break;
            case 8: layer_mma<8><<<grid, 128, smem_for_dil(8)>>>(cur, nxt, Wl, bl, gwl, gbl); break;
        }
        float* t = cur; cur = nxt; nxt = t;
    }

    head_kernel<<<dim3(T_LEN / (256 * 4), B_N), 256>>>(
        cur, mean_w, mean_b, lv_w, lv_b, (float*)d_out);
}

// round 9
// speedup vs baseline: 3.6387x; 1.1040x over previous
#include <cuda_runtime.h>
#include <cuda_bf16.h>
#include <math.h>
#include <stdint.h>

typedef uint32_t u32;
typedef uint64_t u64;

#define T_LEN 262144
#define B_N 8
#define C_N 8
#define K_N 50
#define TILE_M 256

// Ping-pong hidden state [B][C][T]
__device__ float g_h0[B_N * C_N * T_LEN];
__device__ float g_h1[B_N * C_N * T_LEN];
// Layer-0 scalar weights [k][o]
__device__ float g_W0[K_N * C_N];
// Layers 1..17 int8 B fragments: [layer][q(25)][lane(32)] uint4 = (b0_1,b1_1,b0_2,b1_2)
__device__ uint4 g_Bq[17 * 25 * 32];
__device__ float g_wscale[17];
// |h| max bit-patterns; g_hmax_bits[i] = max |input of mma-layer i| (written by layer i-1)
__device__ unsigned int g_hmax_bits[19];

// ---------------------------------------------------------------------------
__device__ __forceinline__ u32 smem_u32(const void* p) {
    return (u32)__cvta_generic_to_shared(p);
}
__device__ __forceinline__ void ldmA(u32& a0, u32& a1, u32& a2, u32& a3, u32 addr) {
    asm volatile("ldmatrix.sync.aligned.m8n8.x4.shared.b16 {%0,%1,%2,%3}, [%4];"
                 : "=r"(a0), "=r"(a1), "=r"(a2), "=r"(a3) : "r"(addr));
}
__device__ __forceinline__ void mma_s8(int* c, u32 a0, u32 a1, u32 a2, u32 a3,
                                       u32 b0, u32 b1) {
    asm volatile("mma.sync.aligned.m16n8k32.row.col.s32.s8.s8.s32 "
                 "{%0,%1,%2,%3},{%4,%5,%6,%7},{%8,%9},{%0,%1,%2,%3};"
                 : "+r"(c[0]), "+r"(c[1]), "+r"(c[2]), "+r"(c[3])
                 : "r"(a0), "r"(a1), "r"(a2), "r"(a3), "r"(b0), "r"(b1));
}
__device__ __forceinline__ u32 pack4i(int a, int b, int c, int d) {
    return (u32)(a & 0xff) | ((u32)(b & 0xff) << 8) |
           ((u32)(c & 0xff) << 16) | ((u32)(d & 0xff) << 24);
}
__device__ __forceinline__ float fast_tanh(float x) {
    x = fminf(fmaxf(x, -30.0f), 30.0f);
    float e = __expf(-2.0f * x);
    return (1.0f - e) / (1.0f + e);
}
__device__ __forceinline__ float fast_sigmoid(float x) {
    x = fminf(fmaxf(x, -30.0f), 30.0f);
    return 1.0f / (1.0f + __expf(-x));
}

// ---------------------------------------------------------------------------
// Weight prep. Block per layer.  l=0: scalar fp32 weights.  l>=1: weight-norm,
// per-layer wmax, 15-bit hi/lo int8 quantization, pack MMA B fragments.
// k-layout per qpair: [tap_a(=shift 2q+1): hi c0-7, lo c0-7 | tap_b(=2q): hi, lo]
// MMA1 B: [Whi_a, 0, Whi_b, 0]  ->  S1 = sum Hhi*Whi
// MMA2 B: [Wlo_a, Whi_a, Wlo_b, Whi_b] -> S2 = sum Hhi*Wlo + Hlo*Whi
// ---------------------------------------------------------------------------
__global__ void prep_weights(const float* __restrict__ v0,
                             const float* __restrict__ g0,
                             const float* __restrict__ vs,
                             const float* __restrict__ gs) {
    int l = blockIdx.x;
    int tid = threadIdx.x;

    if (l == 0) {
        if (tid < C_N) {
            int o = tid;
            float s = 0.0f;
            for (int k = 0; k < K_N; k++) {
                float x = v0[o * K_N + k];
                s += x * x;
            }
            float scale = g0[o] * rsqrtf(s);
            for (int k = 0; k < K_N; k++)
                g_W0[k * C_N + o] = scale * v0[o * K_N + k];
        }
        return;
    }

    __shared__ float osc[C_N];
    __shared__ float w_s[C_N * C_N * K_N];   // 3200 floats
    __shared__ float wred[8];
    __shared__ float swmax;

    const float* v = vs + (size_t)(l - 1) * C_N * C_N * K_N;
    int o = tid >> 5;
    int lane = tid & 31;

    // weight-norm scale per out-channel (warp o)
    {
        float s = 0.0f;
        for (int i = lane; i < C_N * K_N; i += 32) {
            float x = v[o * C_N * K_N + i];
            s += x * x;
        }
        #pragma unroll
        for (int off = 16; off > 0; off >>= 1)
            s += __shfl_down_sync(0xffffffffu, s, off);
        if (lane == 0) osc[o] = gs[(l - 1) * C_N + o] * rsqrtf(s);
    }
    __syncthreads();

    // normalized weights + block max
    float m = 0.0f;
    for (int i = tid; i < 3200; i += 256) {
        float w = v[i] * osc[i / (C_N * K_N)];
        w_s[i] = w;
        m = fmaxf(m, fabsf(w));
    }
    #pragma unroll
    for (int off = 16; off > 0; off >>= 1)
        m = fmaxf(m, __shfl_down_sync(0xffffffffu, m, off));
    if (lane == 0) wred[o] = m;
    __syncthreads();
    if (tid == 0) {
        float wm = wred[0];
        #pragma unroll
        for (int i = 1; i < 8; i++) wm = fmaxf(wm, wred[i]);
        swmax = wm;
        g_wscale[l - 1] = wm / 16256.0f;
    }
    __syncthreads();

    if (tid < 32) {
        int oo = tid >> 2;
        int T = tid & 3;
        float inv = 16256.0f / swmax;
        for (int q = 0; q < 25; q++) {
            int k1 = 48 - 2 * q;   // tap_a (older row)
            int k2 = 49 - 2 * q;   // tap_b
            int ha[8], la[8], hb[8], lb[8];
            #pragma unroll
            for (int c = 0; c < 8; c++) {
                int W = __float2int_rn(w_s[oo * 400 + c * 50 + k1] * inv);
                ha[c] = (W + 64) >> 7;
                la[c] = W - (ha[c] << 7);
                W = __float2int_rn(w_s[oo * 400 + c * 50 + k2] * inv);
                hb[c] = (W + 64) >> 7;
                lb[c] = W - (hb[c] << 7);
            }
            u32 b0_1, b1_1, b0_2, b1_2;
            if (T < 2) {
                int c0 = 4 * T;
                b0_1 = pack4i(ha[c0], ha[c0+1], ha[c0+2], ha[c0+3]);
                b1_1 = pack4i(hb[c0], hb[c0+1], hb[c0+2], hb[c0+3]);
                b0_2 = pack4i(la[c0], la[c0+1], la[c0+2], la[c0+3]);
                b1_2 = pack4i(lb[c0], lb[c0+1], lb[c0+2], lb[c0+3]);
            } else {
                int c0 = 4 * (T - 2);
                b0_1 = 0u;
                b1_1 = 0u;
                b0_2 = pack4i(ha[c0], ha[c0+1], ha[c0+2], ha[c0+3]);
                b1_2 = pack4i(hb[c0], hb[c0+1], hb[c0+2], hb[c0+3]);
            }
            g_Bq[(size_t)(l - 1) * 800 + q * 32 + tid] =
                make_uint4(b0_1, b1_1, b0_2, b1_2);
        }
    }
}

// ---------------------------------------------------------------------------
// Layer 0 (scalar fp32; C_in = 1, dilation 1).  Also records max|h'| -> g_hmax[1].
// ---------------------------------------------------------------------------
__global__ void __launch_bounds__(128)
layer0_kernel(const float* __restrict__ h_in, float* __restrict__ h_out,
              const float* __restrict__ bias, const float* __restrict__ gw,
              const float* __restrict__ gb) {
    constexpr int NP = 4;
    constexpr int TILE = 128 * NP;
    constexpr int HALO = K_N - 1;
    constexpr int HW = TILE + HALO;

    __shared__ __align__(16) float h_s[HW];
    __shared__ __align__(16) float w_s[K_N][C_N];
    __shared__ float gw_s[C_N][C_N];
    __shared__ float b_s[C_N];
    __shared__ float gb_s[C_N];

    const int b = blockIdx.y;
    const int tile0 = blockIdx.x * TILE;
    const int tid = threadIdx.x;

    for (int i = tid; i < K_N * C_N; i += 128) (&w_s[0][0])[i] = g_W0[i];
    for (int i = tid; i < C_N * C_N; i += 128) (&gw_s[0][0])[i] = gw[i];
    if (tid < C_N) { b_s[tid] = bias[tid]; gb_s[tid] = gb[tid]; }

    const float* hb = h_in + (size_t)b * T_LEN;
    for (int j = tid; j < HW; j += 128) {
        int t = tile0 - HALO + j;
        h_s[j] = (t >= 0) ? hb[t] : 0.0f;
    }
    __syncthreads();

    float acc[C_N][NP];
    #pragma unroll
    for (int o = 0; o < C_N; o++) {
        float bv = b_s[o];
        #pragma unroll
        for (int p = 0; p < NP; p++) acc[o][p] = bv;
    }

    #pragma unroll 1
    for (int k = 0; k < K_N; k++) {
        float hv[NP];
        #pragma unroll
        for (int p = 0; p < NP; p++) hv[p] = h_s[tid + k + p * 128];
        float wv[C_N];
        *(float4*)&wv[0] = *(const float4*)&w_s[k][0];
        *(float4*)&wv[4] = *(const float4*)&w_s[k][4];
        #pragma unroll
        for (int o = 0; o < C_N; o++)
            #pragma unroll
            for (int p = 0; p < NP; p++)
                acc[o][p] = fmaf(wv[o], hv[p], acc[o][p]);
    }

    float* ob = h_out + (size_t)b * C_N * T_LEN;
    u32 mx = 0;
    #pragma unroll
    for (int p = 0; p < NP; p++) {
        float prev = h_s[tid + HALO + p * 128];
        #pragma unroll
        for (int o = 0; o < C_N; o++) {
            float gate = gb_s[o];
            #pragma unroll
            for (int c = 0; c < C_N; c++) gate = fmaf(gw_s[o][c], acc[c][p], gate);
            float r = fast_tanh(acc[o][p]) * fast_sigmoid(gate) + prev;
            mx = max(mx, __float_as_uint(fabsf(r)));
            ob[(size_t)o * T_LEN + tile0 + tid + p * 128] = r;
        }
    }
    mx = __reduce_max_sync(0xffffffffu, mx);
    if ((tid & 31) == 0) atomicMax(&g_hmax_bits[1], mx);
}

// ---------------------------------------------------------------------------
// Layers 1..17: int8 m16n8k32 mma.sync, hi/lo packed into K.
// SMEM tile row (16B) = [Hhi c0..7 | Hlo c0..7] of one time row.
// Per (q,z): 1 ldmatrix.x4 + 2 IMMA (S1, S2).  out = s*(16384*S1 + 128*S2).
// ---------------------------------------------------------------------------
template <int DIL>
__global__ void __launch_bounds__(128, 5)
layer_mma(const float* __restrict__ h_in, float* __restrict__ h_out,
          const uint4* __restrict__ Bq,    // [25][32] uint4
          const float* __restrict__ bias, const float* __restrict__ gw,
          const float* __restrict__ gb, int li) {
    constexpr int R = TILE_M / DIL;
    constexpr int R16 = R / 16;
    constexpr int PHROWS = R + 49;
    constexpr int TROWS = TILE_M + 49 * DIL;
    constexpr int PARKPAD = 9;

    extern __shared__ __align__(16) char dyn[];
    char* tile = dyn;                      // int8 tile [TROWS][16]
    float* park = (float*)dyn;             // overlay after MMA
    __shared__ float ctrl[80];             // bias[8], gb[8], gw[64]

    const int b = blockIdx.y;
    const int tile0 = blockIdx.x * TILE_M;
    const int tid = threadIdx.x;
    const int wid = tid >> 5;
    const int lane = tid & 31;

    if (tid < 8) ctrl[tid] = bias[tid];
    else if (tid < 16) ctrl[tid] = gb[tid - 8];
    else if (tid < 80) ctrl[tid] = gw[tid - 16];

    const float hmax = __uint_as_float(g_hmax_bits[li]);
    const float inv_s = 16256.0f / hmax;
    const float s_h = hmax / 16256.0f;
    const float s_w = g_wscale[li - 1];

    // Stage quantized tile, phase-major; one thread per time row (STS.128).
    const float* hb = h_in + (size_t)b * C_N * T_LEN;
    for (int j = tid; j < TROWS; j += 128) {
        int t = tile0 - 49 * DIL + j;
        int Hh[8], Hl[8];
        #pragma unroll
        for (int c = 0; c < C_N; c++) {
            float v = (t >= 0) ? hb[(size_t)c * T_LEN + t] : 0.0f;
            int H = __float2int_rn(v * inv_s);
            Hh[c] = (H + 64) >> 7;
            Hl[c] = H - (Hh[c] << 7);
        }
        int row = j / DIL;
        int p = j % DIL;
        uint4 w;
        w.x = pack4i(Hh[0], Hh[1], Hh[2], Hh[3]);
        w.y = pack4i(Hh[4], Hh[5], Hh[6], Hh[7]);
        w.z = pack4i(Hl[0], Hl[1], Hl[2], Hl[3]);
        w.w = pack4i(Hl[4], Hl[5], Hl[6], Hl[7]);
        *(uint4*)&tile[(p * PHROWS + row) * 16] = w;
    }
    __syncthreads();

    // Per-z ldmatrix base offsets (16B rows; identical pattern to bf16 version).
    const int rowlane = (lane & 15) + (lane >> 4);
    u32 zb[4];
    #pragma unroll
    for (int z = 0; z < 4; z++) {
        int st = wid * 4 + z;
        int p = st / R16;
        int sub = st % R16;
        zb[z] = (u32)((p * PHROWS + sub * 16 + 48 + rowlane) * 16);
    }

    const u32 t32 = smem_u32(tile);

    int acc1[4][4], acc2[4][4];
    #pragma unroll
    for (int z = 0; z < 4; z++)
        #pragma unroll
        for (int q = 0; q < 4; q++) { acc1[z][q] = 0; acc2[z][q] = 0; }

    {
        const uint4* bw = Bq + lane;
        uint4 bb = *bw;                      // prefetch q=0
        #pragma unroll 5
        for (int q = 0; q < 25; q++) {
            uint4 nb = (q < 24) ? bw[(q + 1) * 32] : bb;
            u32 off = (u32)(q * 32);
            #pragma unroll
            for (int z = 0; z < 4; z++) {
                u32 a0, a1, a2, a3;
                ldmA(a0, a1, a2, a3, t32 + zb[z] - off);
                mma_s8(acc1[z], a0, a1, a2, a3, bb.x, bb.y);
                mma_s8(acc2[z], a0, a1, a2, a3, bb.z, bb.w);
            }
            bb = nb;
        }
    }

    // Park combined fp32 conv outputs (overlay on tile).
    const float c1 = s_h * s_w * 16384.0f;
    const float c2 = s_h * s_w * 128.0f;
    __syncthreads();
    {
        const int g = lane >> 2;
        const int tig = lane & 3;
        #pragma unroll
        for (int z = 0; z < 4; z++) {
            int st = wid * 4 + z;
            int p = st / R16;
            int sub = st % R16;
            int i0 = (sub * 16 + g) * DIL + p;
            int i1 = i0 + 8 * DIL;
            park[i0 * PARKPAD + 2 * tig]     = c1 * (float)acc1[z][0] + c2 * (float)acc2[z][0];
            park[i0 * PARKPAD + 2 * tig + 1] = c1 * (float)acc1[z][1] + c2 * (float)acc2[z][1];
            park[i1 * PARKPAD + 2 * tig]     = c1 * (float)acc1[z][2] + c2 * (float)acc2[z][2];
            park[i1 * PARKPAD + 2 * tig + 1] = c1 * (float)acc1[z][3] + c2 * (float)acc2[z][3];
        }
    }
    __syncthreads();

    // Epilogue: rows tid and tid+128; fp32 residual from gmem; track out max.
    float* ob = h_out + (size_t)b * C_N * T_LEN;
    u32 mx = 0;
    #pragma unroll
    for (int half = 0; half < 2; half++) {
        const int r = tid + half * 128;
        float outv[C_N];
        #pragma unroll
        for (int o = 0; o < C_N; o++) outv[o] = park[r * PARKPAD + o] + ctrl[o];
        #pragma unroll
        for (int o = 0; o < C_N; o++) {
            float gate = ctrl[8 + o];
            #pragma unroll
            for (int c = 0; c < C_N; c++)
                gate = fmaf(ctrl[16 + o * 8 + c], outv[c], gate);
            float prev = hb[(size_t)o * T_LEN + tile0 + r];
            float rr = fast_tanh(outv[o]) * fast_sigmoid(gate) + prev;
            mx = max(mx, __float_as_uint(fabsf(rr)));
            ob[(size_t)o * T_LEN + tile0 + r] = rr;
        }
    }
    mx = __reduce_max_sync(0xffffffffu, mx);
    if (lane == 0) atomicMax(&g_hmax_bits[li + 1], mx);
}

// ---------------------------------------------------------------------------
// Head
// ---------------------------------------------------------------------------
__global__ void __launch_bounds__(256)
head_kernel(const float* __restrict__ h,
            const float* __restrict__ mean_w, const float* __restrict__ mean_b,
            const float* __restrict__ lv_w, const float* __restrict__ lv_b,
            float* __restrict__ out) {
    const int b = blockIdx.y;
    const int t0 = (blockIdx.x * 256 + threadIdx.x) * 4;
    if (t0 >= T_LEN) return;
    const float* hbp = h + (size_t)b * C_N * T_LEN;
    float m[4], lv[4];
    float mb = mean_b[0], lb = lv_b[0];
    #pragma unroll
    for (int p = 0; p < 4; p++) { m[p] = mb; lv[p] = lb; }
    #pragma unroll
    for (int c = 0; c < C_N; c++) {
        float4 hv = *(const float4*)&hbp[(size_t)c * T_LEN + t0];
        float mw = mean_w[c], lw = lv_w[c];
        m[0] = fmaf(mw, hv.x, m[0]); lv[0] = fmaf(lw, hv.x, lv[0]);
        m[1] = fmaf(mw, hv.y, m[1]); lv[1] = fmaf(lw, hv.y, lv[1]);
        m[2] = fmaf(mw, hv.z, m[2]); lv[2] = fmaf(lw, hv.z, lv[2]);
        m[3] = fmaf(mw, hv.w, m[3]); lv[3] = fmaf(lw, hv.w, lv[3]);
    }
    float s[4];
    #pragma unroll
    for (int p = 0; p < 4; p++) s[p] = expf(0.5f * lv[p]);
    *(float4*)&out[(size_t)b * T_LEN + t0] = make_float4(m[0], m[1], m[2], m[3]);
    *(float4*)&out[(size_t)B_N * T_LEN + (size_t)b * T_LEN + t0] =
        make_float4(s[0], s[1], s[2], s[3]);
}

// ---------------------------------------------------------------------------
static int smem_for_dil(int d) {
    int tile = (TILE_M + 49 * d) * 16;     // int8 tile
    int park = TILE_M * 9 * 4;
    return tile > park ? tile : park;
}

extern "C" void kernel_launch(void* const* d_in, const int* in_sizes, int n_in,
                              void* d_out, int out_size) {
    (void)in_sizes; (void)n_in; (void)out_size;
    const float* x      = (const float*)d_in[0];
    const float* v0     = (const float*)d_in[1];
    const float* g0     = (const float*)d_in[2];
    const float* b0     = (const float*)d_in[3];
    const float* gw0    = (const float*)d_in[4];
    const float* gb0    = (const float*)d_in[5];
    const float* vs     = (const float*)d_in[6];
    const float* gs     = (const float*)d_in[7];
    const float* bs     = (const float*)d_in[8];
    const float* gws    = (const float*)d_in[9];
    const float* gbs    = (const float*)d_in[10];
    const float* mean_w = (const float*)d_in[11];
    const float* mean_b = (const float*)d_in[12];
    const float* lv_w   = (const float*)d_in[13];
    const float* lv_b   = (const float*)d_in[14];

    float *bufA, *bufB;
    uint4* Bq;
    cudaGetSymbolAddress((void**)&bufA, g_h0);
    cudaGetSymbolAddress((void**)&bufB, g_h1);
    cudaGetSymbolAddress((void**)&Bq, g_Bq);

    cudaFuncSetAttribute(layer_mma<1>, cudaFuncAttributeMaxDynamicSharedMemorySize, smem_for_dil(1));
    cudaFuncSetAttribute(layer_mma<2>, cudaFuncAttributeMaxDynamicSharedMemorySize, smem_for_dil(2));
    cudaFuncSetAttribute(layer_mma<4>, cudaFuncAttributeMaxDynamicSharedMemorySize, smem_for_dil(4));
    cudaFuncSetAttribute(layer_mma<8>, cudaFuncAttributeMaxDynamicSharedMemorySize, smem_for_dil(8));

    prep_weights<<<18, 256>>>(v0, g0, vs, gs);

    layer0_kernel<<<dim3(T_LEN / 512, B_N), 128>>>(x, bufA, b0, gw0, gb0);

    static const int dils[18] = {1,1,1,1,1,1,1,2,2,2,2,4,4,4,4,8,8,8};
    dim3 grid(T_LEN / TILE_M, B_N);
    float* cur = bufA;
    float* nxt = bufB;
    for (int i = 1; i < 18; i++) {
        const uint4* Wl  = Bq + (size_t)(i - 1) * 800;
        const float* bl  = bs  + (i - 1) * C_N;
        const float* gwl = gws + (i - 1) * C_N * C_N;
        const float* gbl = gbs + (i - 1) * C_N;
        switch (dils[i]) {
            case 1: layer_mma<1><<<grid, 128, smem_for_dil(1)>>>(cur, nxt, Wl, bl, gwl, gbl, i); break;
            case 2: layer_mma<2><<<grid, 128, smem_for_dil(2)>>>(cur, nxt, Wl, bl, gwl, gbl, i); break;
            case 4: layer_mma<4><<<grid, 128, smem_for_dil(4)>>>(cur, nxt, Wl, bl, gwl, gbl, i); break;
            case 8: layer_mma<8><<<grid, 128, smem_for_dil(8)>>>(cur, nxt, Wl, bl, gwl, gbl, i); break;
        }
        float* t = cur; cur = nxt; nxt = t;
    }

    head_kernel<<<dim3(T_LEN / (256 * 4), B_N), 256>>>(
        cur, mean_w, mean_b, lv_w, lv_b, (float*)d_out);
}

// round 10
// speedup vs baseline: 4.0529x; 1.1138x over previous
#include <cuda_runtime.h>
#include <cuda_bf16.h>
#include <math.h>
#include <stdint.h>

typedef uint32_t u32;
typedef uint64_t u64;

#define T_LEN 262144
#define B_N 8
#define C_N 8
#define K_N 50
#define TILE_M 256

// Ping-pong hidden state [B][C][T]
__device__ float g_h0[B_N * C_N * T_LEN];
__device__ float g_h1[B_N * C_N * T_LEN];
// Layer-0 scalar weights [k][o]
__device__ float g_W0[K_N * C_N];
// Layers 1..17 int8 B fragments: [layer][q(25)][lane(32)] uint4 = (b0_1,b1_1,b0_2,b1_2)
__device__ uint4 g_Bq[17 * 25 * 32];
__device__ float g_wscale[17];
// |h| max bit-patterns; g_hmax_bits[i] = max |input of mma-layer i| (written by layer i-1)
__device__ unsigned int g_hmax_bits[19];

// ---------------------------------------------------------------------------
__device__ __forceinline__ u32 smem_u32(const void* p) {
    return (u32)__cvta_generic_to_shared(p);
}
__device__ __forceinline__ void ldmA(u32& a0, u32& a1, u32& a2, u32& a3, u32 addr) {
    asm volatile("ldmatrix.sync.aligned.m8n8.x4.shared.b16 {%0,%1,%2,%3}, [%4];"
                 : "=r"(a0), "=r"(a1), "=r"(a2), "=r"(a3) : "r"(addr));
}
__device__ __forceinline__ void mma_s8(int* c, u32 a0, u32 a1, u32 a2, u32 a3,
                                       u32 b0, u32 b1) {
    asm volatile("mma.sync.aligned.m16n8k32.row.col.s32.s8.s8.s32 "
                 "{%0,%1,%2,%3},{%4,%5,%6,%7},{%8,%9},{%0,%1,%2,%3};"
                 : "+r"(c[0]), "+r"(c[1]), "+r"(c[2]), "+r"(c[3])
                 : "r"(a0), "r"(a1), "r"(a2), "r"(a3), "r"(b0), "r"(b1));
}
__device__ __forceinline__ u32 pack4i(int a, int b, int c, int d) {
    return (u32)(a & 0xff) | ((u32)(b & 0xff) << 8) |
           ((u32)(c & 0xff) << 16) | ((u32)(d & 0xff) << 24);
}
__device__ __forceinline__ float fast_tanh(float x) {
    x = fminf(fmaxf(x, -30.0f), 30.0f);
    float e = __expf(-2.0f * x);
    return (1.0f - e) / (1.0f + e);
}
__device__ __forceinline__ float fast_sigmoid(float x) {
    x = fminf(fmaxf(x, -30.0f), 30.0f);
    return 1.0f / (1.0f + __expf(-x));
}

// ---------------------------------------------------------------------------
// Weight prep. Block per layer.  l=0: scalar fp32 weights.  l>=1: weight-norm,
// per-layer wmax, 15-bit hi/lo int8 quantization, pack MMA B fragments.
// MMA1 B: [Whi_a, 0, Whi_b, 0]  ->  S1 = sum Hhi*Whi
// MMA2 B: [Wlo_a, Whi_a, Wlo_b, Whi_b] -> S2 = sum Hhi*Wlo + Hlo*Whi
// ---------------------------------------------------------------------------
__global__ void prep_weights(const float* __restrict__ v0,
                             const float* __restrict__ g0,
                             const float* __restrict__ vs,
                             const float* __restrict__ gs) {
    int l = blockIdx.x;
    int tid = threadIdx.x;

    if (l == 0) {
        if (tid < C_N) {
            int o = tid;
            float s = 0.0f;
            for (int k = 0; k < K_N; k++) {
                float x = v0[o * K_N + k];
                s += x * x;
            }
            float scale = g0[o] * rsqrtf(s);
            for (int k = 0; k < K_N; k++)
                g_W0[k * C_N + o] = scale * v0[o * K_N + k];
        }
        return;
    }

    __shared__ float osc[C_N];
    __shared__ float w_s[C_N * C_N * K_N];   // 3200 floats
    __shared__ float wred[8];
    __shared__ float swmax;

    const float* v = vs + (size_t)(l - 1) * C_N * C_N * K_N;
    int o = tid >> 5;
    int lane = tid & 31;

    // weight-norm scale per out-channel (warp o)
    {
        float s = 0.0f;
        for (int i = lane; i < C_N * K_N; i += 32) {
            float x = v[o * C_N * K_N + i];
            s += x * x;
        }
        #pragma unroll
        for (int off = 16; off > 0; off >>= 1)
            s += __shfl_down_sync(0xffffffffu, s, off);
        if (lane == 0) osc[o] = gs[(l - 1) * C_N + o] * rsqrtf(s);
    }
    __syncthreads();

    // normalized weights + block max
    float m = 0.0f;
    for (int i = tid; i < 3200; i += 256) {
        float w = v[i] * osc[i / (C_N * K_N)];
        w_s[i] = w;
        m = fmaxf(m, fabsf(w));
    }
    #pragma unroll
    for (int off = 16; off > 0; off >>= 1)
        m = fmaxf(m, __shfl_down_sync(0xffffffffu, m, off));
    if (lane == 0) wred[o] = m;
    __syncthreads();
    if (tid == 0) {
        float wm = wred[0];
        #pragma unroll
        for (int i = 1; i < 8; i++) wm = fmaxf(wm, wred[i]);
        swmax = wm;
        g_wscale[l - 1] = wm / 16256.0f;
    }
    __syncthreads();

    if (tid < 32) {
        int oo = tid >> 2;
        int T = tid & 3;
        float inv = 16256.0f / swmax;
        for (int q = 0; q < 25; q++) {
            int k1 = 48 - 2 * q;   // tap_a (older row)
            int k2 = 49 - 2 * q;   // tap_b
            int ha[8], la[8], hb[8], lb[8];
            #pragma unroll
            for (int c = 0; c < 8; c++) {
                int W = __float2int_rn(w_s[oo * 400 + c * 50 + k1] * inv);
                ha[c] = (W + 64) >> 7;
                la[c] = W - (ha[c] << 7);
                W = __float2int_rn(w_s[oo * 400 + c * 50 + k2] * inv);
                hb[c] = (W + 64) >> 7;
                lb[c] = W - (hb[c] << 7);
            }
            u32 b0_1, b1_1, b0_2, b1_2;
            if (T < 2) {
                int c0 = 4 * T;
                b0_1 = pack4i(ha[c0], ha[c0+1], ha[c0+2], ha[c0+3]);
                b1_1 = pack4i(hb[c0], hb[c0+1], hb[c0+2], hb[c0+3]);
                b0_2 = pack4i(la[c0], la[c0+1], la[c0+2], la[c0+3]);
                b1_2 = pack4i(lb[c0], lb[c0+1], lb[c0+2], lb[c0+3]);
            } else {
                int c0 = 4 * (T - 2);
                b0_1 = 0u;
                b1_1 = 0u;
                b0_2 = pack4i(ha[c0], ha[c0+1], ha[c0+2], ha[c0+3]);
                b1_2 = pack4i(hb[c0], hb[c0+1], hb[c0+2], hb[c0+3]);
            }
            g_Bq[(size_t)(l - 1) * 800 + q * 32 + tid] =
                make_uint4(b0_1, b1_1, b0_2, b1_2);
        }
    }
}

// ---------------------------------------------------------------------------
// Layer 0 (scalar fp32; C_in = 1, dilation 1).  Records max|h'| -> g_hmax[1].
// ---------------------------------------------------------------------------
__global__ void __launch_bounds__(128)
layer0_kernel(const float* __restrict__ h_in, float* __restrict__ h_out,
              const float* __restrict__ bias, const float* __restrict__ gw,
              const float* __restrict__ gb) {
    constexpr int NP = 4;
    constexpr int TILE = 128 * NP;
    constexpr int HALO = K_N - 1;
    constexpr int HW = TILE + HALO;

    __shared__ __align__(16) float h_s[HW];
    __shared__ __align__(16) float w_s[K_N][C_N];
    __shared__ float gw_s[C_N][C_N];
    __shared__ float b_s[C_N];
    __shared__ float gb_s[C_N];

    const int b = blockIdx.y;
    const int tile0 = blockIdx.x * TILE;
    const int tid = threadIdx.x;

    for (int i = tid; i < K_N * C_N; i += 128) (&w_s[0][0])[i] = g_W0[i];
    for (int i = tid; i < C_N * C_N; i += 128) (&gw_s[0][0])[i] = gw[i];
    if (tid < C_N) { b_s[tid] = bias[tid]; gb_s[tid] = gb[tid]; }

    const float* hb = h_in + (size_t)b * T_LEN;
    for (int j = tid; j < HW; j += 128) {
        int t = tile0 - HALO + j;
        h_s[j] = (t >= 0) ? hb[t] : 0.0f;
    }
    __syncthreads();

    float acc[C_N][NP];
    #pragma unroll
    for (int o = 0; o < C_N; o++) {
        float bv = b_s[o];
        #pragma unroll
        for (int p = 0; p < NP; p++) acc[o][p] = bv;
    }

    #pragma unroll 1
    for (int k = 0; k < K_N; k++) {
        float hv[NP];
        #pragma unroll
        for (int p = 0; p < NP; p++) hv[p] = h_s[tid + k + p * 128];
        float wv[C_N];
        *(float4*)&wv[0] = *(const float4*)&w_s[k][0];
        *(float4*)&wv[4] = *(const float4*)&w_s[k][4];
        #pragma unroll
        for (int o = 0; o < C_N; o++)
            #pragma unroll
            for (int p = 0; p < NP; p++)
                acc[o][p] = fmaf(wv[o], hv[p], acc[o][p]);
    }

    float* ob = h_out + (size_t)b * C_N * T_LEN;
    u32 mx = 0;
    #pragma unroll
    for (int p = 0; p < NP; p++) {
        float prev = h_s[tid + HALO + p * 128];
        #pragma unroll
        for (int o = 0; o < C_N; o++) {
            float gate = gb_s[o];
            #pragma unroll
            for (int c = 0; c < C_N; c++) gate = fmaf(gw_s[o][c], acc[c][p], gate);
            float r = fast_tanh(acc[o][p]) * fast_sigmoid(gate) + prev;
            mx = max(mx, __float_as_uint(fabsf(r)));
            ob[(size_t)o * T_LEN + tile0 + tid + p * 128] = r;
        }
    }
    mx = __reduce_max_sync(0xffffffffu, mx);
    if ((tid & 31) == 0) atomicMax(&g_hmax_bits[1], mx);
}

// ---------------------------------------------------------------------------
// Layers 1..17: int8 m16n8k32 mma.sync, hi/lo packed into K.
// SMEM: int8 tile (overlaid by park after MMA) + separate fp32 residual
// buffer filled during staging (epilogue reads SMEM, not gmem).
// ---------------------------------------------------------------------------
template <int DIL>
__global__ void __launch_bounds__(128, 6)
layer_mma(const float* __restrict__ h_in, float* __restrict__ h_out,
          const uint4* __restrict__ Bq,    // [25][32] uint4
          const float* __restrict__ bias, const float* __restrict__ gw,
          const float* __restrict__ gb, int li) {
    constexpr int R = TILE_M / DIL;
    constexpr int R16 = R / 16;
    constexpr int PHROWS = R + 49;
    constexpr int TROWS = TILE_M + 49 * DIL;
    constexpr int PARKPAD = 9;
    constexpr int TILEB = TROWS * 16;
    constexpr int PARKB = TILE_M * PARKPAD * 4;
    constexpr int R1 = (((TILEB > PARKB) ? TILEB : PARKB) + 15) & ~15;

    extern __shared__ __align__(16) char dyn[];
    char* tile = dyn;                      // int8 tile [TROWS][16]
    float* park = (float*)dyn;             // overlay after MMA
    float* f32res = (float*)(dyn + R1);    // fp32 residual [TILE_M][8]
    __shared__ float ctrl[80];             // bias[8], gb[8], gw[64]

    const int b = blockIdx.y;
    const int tile0 = blockIdx.x * TILE_M;
    const int tid = threadIdx.x;
    const int wid = tid >> 5;
    const int lane = tid & 31;

    if (tid < 8) ctrl[tid] = bias[tid];
    else if (tid < 16) ctrl[tid] = gb[tid - 8];
    else if (tid < 80) ctrl[tid] = gw[tid - 16];

    const float hmax = __uint_as_float(g_hmax_bits[li]);
    const float inv_s = 16256.0f / hmax;
    const float s_h = hmax / 16256.0f;
    const float s_w = g_wscale[li - 1];

    // Stage quantized tile, phase-major; one thread per time row (STS.128).
    // Tile rows (r >= 0) also parked as fp32 for the epilogue residual.
    const float* hb = h_in + (size_t)b * C_N * T_LEN;
    for (int j = tid; j < TROWS; j += 128) {
        int t = tile0 - 49 * DIL + j;
        float v[C_N];
        int Hh[8], Hl[8];
        #pragma unroll
        for (int c = 0; c < C_N; c++) {
            v[c] = (t >= 0) ? hb[(size_t)c * T_LEN + t] : 0.0f;
            int H = __float2int_rn(v[c] * inv_s);
            Hh[c] = (H + 64) >> 7;
            Hl[c] = H - (Hh[c] << 7);
        }
        int row = j / DIL;
        int p = j % DIL;
        uint4 w;
        w.x = pack4i(Hh[0], Hh[1], Hh[2], Hh[3]);
        w.y = pack4i(Hh[4], Hh[5], Hh[6], Hh[7]);
        w.z = pack4i(Hl[0], Hl[1], Hl[2], Hl[3]);
        w.w = pack4i(Hl[4], Hl[5], Hl[6], Hl[7]);
        *(uint4*)&tile[(p * PHROWS + row) * 16] = w;
        int r = j - 49 * DIL;
        if (r >= 0) {
            *(float4*)&f32res[r * 8] = make_float4(v[0], v[1], v[2], v[3]);
            *(float4*)&f32res[r * 8 + 4] = make_float4(v[4], v[5], v[6], v[7]);
        }
    }
    __syncthreads();

    // Per-z ldmatrix base offsets (16B rows).
    const int rowlane = (lane & 15) + (lane >> 4);
    u32 zb[4];
    #pragma unroll
    for (int z = 0; z < 4; z++) {
        int st = wid * 4 + z;
        int p = st / R16;
        int sub = st % R16;
        zb[z] = (u32)((p * PHROWS + sub * 16 + 48 + rowlane) * 16);
    }

    const u32 t32 = smem_u32(tile);

    int acc1[4][4], acc2[4][4];
    #pragma unroll
    for (int z = 0; z < 4; z++)
        #pragma unroll
        for (int q = 0; q < 4; q++) { acc1[z][q] = 0; acc2[z][q] = 0; }

    {
        const uint4* bw = Bq + lane;
        uint4 bb = *bw;                      // prefetch q=0
        #pragma unroll 5
        for (int q = 0; q < 25; q++) {
            uint4 nb = (q < 24) ? bw[(q + 1) * 32] : bb;
            u32 off = (u32)(q * 32);
            #pragma unroll
            for (int z = 0; z < 4; z++) {
                u32 a0, a1, a2, a3;
                ldmA(a0, a1, a2, a3, t32 + zb[z] - off);
                mma_s8(acc1[z], a0, a1, a2, a3, bb.x, bb.y);
                mma_s8(acc2[z], a0, a1, a2, a3, bb.z, bb.w);
            }
            bb = nb;
        }
    }

    // Park combined fp32 conv outputs (overlay on tile).
    const float c1 = s_h * s_w * 16384.0f;
    const float c2 = s_h * s_w * 128.0f;
    __syncthreads();
    {
        const int g = lane >> 2;
        const int tig = lane & 3;
        #pragma unroll
        for (int z = 0; z < 4; z++) {
            int st = wid * 4 + z;
            int p = st / R16;
            int sub = st % R16;
            int i0 = (sub * 16 + g) * DIL + p;
            int i1 = i0 + 8 * DIL;
            park[i0 * PARKPAD + 2 * tig]     = c1 * (float)acc1[z][0] + c2 * (float)acc2[z][0];
            park[i0 * PARKPAD + 2 * tig + 1] = c1 * (float)acc1[z][1] + c2 * (float)acc2[z][1];
            park[i1 * PARKPAD + 2 * tig]     = c1 * (float)acc1[z][2] + c2 * (float)acc2[z][2];
            park[i1 * PARKPAD + 2 * tig + 1] = c1 * (float)acc1[z][3] + c2 * (float)acc2[z][3];
        }
    }
    __syncthreads();

    // Epilogue: rows tid and tid+128; residual from SMEM; track out max.
    float* ob = h_out + (size_t)b * C_N * T_LEN;
    u32 mx = 0;
    #pragma unroll
    for (int half = 0; half < 2; half++) {
        const int r = tid + half * 128;
        float outv[C_N];
        #pragma unroll
        for (int o = 0; o < C_N; o++) outv[o] = park[r * PARKPAD + o] + ctrl[o];
        float4 p0 = *(const float4*)&f32res[r * 8];
        float4 p1 = *(const float4*)&f32res[r * 8 + 4];
        float prev[C_N] = {p0.x, p0.y, p0.z, p0.w, p1.x, p1.y, p1.z, p1.w};
        #pragma unroll
        for (int o = 0; o < C_N; o++) {
            float gate = ctrl[8 + o];
            #pragma unroll
            for (int c = 0; c < C_N; c++)
                gate = fmaf(ctrl[16 + o * 8 + c], outv[c], gate);
            float rr = fast_tanh(outv[o]) * fast_sigmoid(gate) + prev[o];
            mx = max(mx, __float_as_uint(fabsf(rr)));
            ob[(size_t)o * T_LEN + tile0 + r] = rr;
        }
    }
    mx = __reduce_max_sync(0xffffffffu, mx);
    if (lane == 0) atomicMax(&g_hmax_bits[li + 1], mx);
}

// ---------------------------------------------------------------------------
// Head
// ---------------------------------------------------------------------------
__global__ void __launch_bounds__(256)
head_kernel(const float* __restrict__ h,
            const float* __restrict__ mean_w, const float* __restrict__ mean_b,
            const float* __restrict__ lv_w, const float* __restrict__ lv_b,
            float* __restrict__ out) {
    const int b = blockIdx.y;
    const int t0 = (blockIdx.x * 256 + threadIdx.x) * 4;
    if (t0 >= T_LEN) return;
    const float* hbp = h + (size_t)b * C_N * T_LEN;
    float m[4], lv[4];
    float mb = mean_b[0], lb = lv_b[0];
    #pragma unroll
    for (int p = 0; p < 4; p++) { m[p] = mb; lv[p] = lb; }
    #pragma unroll
    for (int c = 0; c < C_N; c++) {
        float4 hv = *(const float4*)&hbp[(size_t)c * T_LEN + t0];
        float mw = mean_w[c], lw = lv_w[c];
        m[0] = fmaf(mw, hv.x, m[0]); lv[0] = fmaf(lw, hv.x, lv[0]);
        m[1] = fmaf(mw, hv.y, m[1]); lv[1] = fmaf(lw, hv.y, lv[1]);
        m[2] = fmaf(mw, hv.z, m[2]); lv[2] = fmaf(lw, hv.z, lv[2]);
        m[3] = fmaf(mw, hv.w, m[3]); lv[3] = fmaf(lw, hv.w, lv[3]);
    }
    float s[4];
    #pragma unroll
    for (int p = 0; p < 4; p++) s[p] = expf(0.5f * lv[p]);
    *(float4*)&out[(size_t)b * T_LEN + t0] = make_float4(m[0], m[1], m[2], m[3]);
    *(float4*)&out[(size_t)B_N * T_LEN + (size_t)b * T_LEN + t0] =
        make_float4(s[0], s[1], s[2], s[3]);
}

// ---------------------------------------------------------------------------
static int smem_for_dil(int d) {
    int tileb = (TILE_M + 49 * d) * 16;
    int parkb = TILE_M * 9 * 4;
    int r1 = (tileb > parkb ? tileb : parkb);
    r1 = (r1 + 15) & ~15;
    return r1 + TILE_M * 8 * 4;            // + fp32 residual buffer
}

extern "C" void kernel_launch(void* const* d_in, const int* in_sizes, int n_in,
                              void* d_out, int out_size) {
    (void)in_sizes; (void)n_in; (void)out_size;
    const float* x      = (const float*)d_in[0];
    const float* v0     = (const float*)d_in[1];
    const float* g0     = (const float*)d_in[2];
    const float* b0     = (const float*)d_in[3];
    const float* gw0    = (const float*)d_in[4];
    const float* gb0    = (const float*)d_in[5];
    const float* vs     = (const float*)d_in[6];
    const float* gs     = (const float*)d_in[7];
    const float* bs     = (const float*)d_in[8];
    const float* gws    = (const float*)d_in[9];
    const float* gbs    = (const float*)d_in[10];
    const float* mean_w = (const float*)d_in[11];
    const float* mean_b = (const float*)d_in[12];
    const float* lv_w   = (const float*)d_in[13];
    const float* lv_b   = (const float*)d_in[14];

    float *bufA, *bufB;
    uint4* Bq;
    cudaGetSymbolAddress((void**)&bufA, g_h0);
    cudaGetSymbolAddress((void**)&bufB, g_h1);
    cudaGetSymbolAddress((void**)&Bq, g_Bq);

    cudaFuncSetAttribute(layer_mma<1>, cudaFuncAttributeMaxDynamicSharedMemorySize, smem_for_dil(1));
    cudaFuncSetAttribute(layer_mma<2>, cudaFuncAttributeMaxDynamicSharedMemorySize, smem_for_dil(2));
    cudaFuncSetAttribute(layer_mma<4>, cudaFuncAttributeMaxDynamicSharedMemorySize, smem_for_dil(4));
    cudaFuncSetAttribute(layer_mma<8>, cudaFuncAttributeMaxDynamicSharedMemorySize, smem_for_dil(8));

    prep_weights<<<18, 256>>>(v0, g0, vs, gs);

    layer0_kernel<<<dim3(T_LEN / 512, B_N), 128>>>(x, bufA, b0, gw0, gb0);

    static const int dils[18] = {1,1,1,1,1,1,1,2,2,2,2,4,4,4,4,8,8,8};
    dim3 grid(T_LEN / TILE_M, B_N);
    float* cur = bufA;
    float* nxt = bufB;
    for (int i = 1; i < 18; i++) {
        const uint4* Wl  = Bq + (size_t)(i - 1) * 800;
        const float* bl  = bs  + (i - 1) * C_N;
        const float* gwl = gws + (i - 1) * C_N * C_N;
        const float* gbl = gbs + (i - 1) * C_N;
        switch (dils[i]) {
            case 1: layer_mma<1><<<grid, 128, smem_for_dil(1)>>>(cur, nxt, Wl, bl, gwl, gbl, i); break;
            case 2: layer_mma<2><<<grid, 128, smem_for_dil(2)>>>(cur, nxt, Wl, bl, gwl, gbl, i); break;
            case 4: layer_mma<4><<<grid, 128, smem_for_dil(4)>>>(cur, nxt, Wl, bl, gwl, gbl, i); break;
            case 8: layer_mma<8><<<grid, 128, smem_for_dil(8)>>>(cur, nxt, Wl, bl, gwl, gbl, i); break;
        }
        float* t = cur; cur = nxt; nxt = t;
    }

    head_kernel<<<dim3(T_LEN / (256 * 4), B_N), 256>>>(
        cur, mean_w, mean_b, lv_w, lv_b, (float*)d_out);
}

// round 12
// speedup vs baseline: 4.3091x; 1.0632x over previous
#include <cuda_runtime.h>
#include <cuda_bf16.h>
#include <math.h>
#include <stdint.h>

typedef uint32_t u32;
typedef uint64_t u64;

#define T_LEN 262144
#define B_N 8
#define C_N 8
#define K_N 50
#define TILE_M 256

// Ping-pong hidden state [B][C][T]
__device__ float g_h0[B_N * C_N * T_LEN];
__device__ float g_h1[B_N * C_N * T_LEN];
// Layer-0 scalar weights [k][o]
__device__ float g_W0[K_N * C_N];
// Layers 1..17 int8 B fragments (compressed): [layer][q(25)][lane(32)] uint2 = (b0_2,b1_2)
// MMA1's operands are derived in-kernel via shfl from lane+2 (zero on (lane&3)>=2).
__device__ uint2 g_Bq[17 * 25 * 32];
__device__ float g_wscale[17];
// |h| max bit-patterns; g_hmax_bits[i] = max |input of mma-layer i| (written by layer i-1)
__device__ unsigned int g_hmax_bits[19];

// ---------------------------------------------------------------------------
__device__ __forceinline__ u32 smem_u32(const void* p) {
    return (u32)__cvta_generic_to_shared(p);
}
__device__ __forceinline__ void ldmA(u32& a0, u32& a1, u32& a2, u32& a3, u32 addr) {
    asm volatile("ldmatrix.sync.aligned.m8n8.x4.shared.b16 {%0,%1,%2,%3}, [%4];"
                 : "=r"(a0), "=r"(a1), "=r"(a2), "=r"(a3) : "r"(addr));
}
__device__ __forceinline__ void mma_s8(int* c, u32 a0, u32 a1, u32 a2, u32 a3,
                                       u32 b0, u32 b1) {
    asm volatile("mma.sync.aligned.m16n8k32.row.col.s32.s8.s8.s32 "
                 "{%0,%1,%2,%3},{%4,%5,%6,%7},{%8,%9},{%0,%1,%2,%3};"
                 : "+r"(c[0]), "+r"(c[1]), "+r"(c[2]), "+r"(c[3])
                 : "r"(a0), "r"(a1), "r"(a2), "r"(a3), "r"(b0), "r"(b1));
}
__device__ __forceinline__ u32 pack4i(int a, int b, int c, int d) {
    return (u32)(a & 0xff) | ((u32)(b & 0xff) << 8) |
           ((u32)(c & 0xff) << 16) | ((u32)(d & 0xff) << 24);
}
__device__ __forceinline__ float fast_tanh(float x) {
    x = fminf(fmaxf(x, -30.0f), 30.0f);
    float e = __expf(-2.0f * x);
    return (1.0f - e) / (1.0f + e);
}
__device__ __forceinline__ float fast_sigmoid(float x) {
    x = fminf(fmaxf(x, -30.0f), 30.0f);
    return 1.0f / (1.0f + __expf(-x));
}

// ---------------------------------------------------------------------------
// Weight prep. Block per layer.  l=0: scalar fp32 weights.  l>=1: weight-norm,
// per-layer wmax, 15-bit hi/lo int8 quantization, pack MMA B fragments.
// Stored (compressed): (b0_2,b1_2) = lanes T<2: (lo taps), T>=2: (hi taps).
// MMA1 B (= [Whi,0]) is reconstructed in-kernel: shfl from lane+2, mask T>=2.
// ---------------------------------------------------------------------------
__global__ void prep_weights(const float* __restrict__ v0,
                             const float* __restrict__ g0,
                             const float* __restrict__ vs,
                             const float* __restrict__ gs) {
    int l = blockIdx.x;
    int tid = threadIdx.x;

    if (l == 0) {
        if (tid < C_N) {
            int o = tid;
            float s = 0.0f;
            for (int k = 0; k < K_N; k++) {
                float x = v0[o * K_N + k];
                s += x * x;
            }
            float scale = g0[o] * rsqrtf(s);
            for (int k = 0; k < K_N; k++)
                g_W0[k * C_N + o] = scale * v0[o * K_N + k];
        }
        return;
    }

    __shared__ float osc[C_N];
    __shared__ float w_s[C_N * C_N * K_N];   // 3200 floats
    __shared__ float wred[8];
    __shared__ float swmax;

    const float* v = vs + (size_t)(l - 1) * C_N * C_N * K_N;
    int o = tid >> 5;
    int lane = tid & 31;

    // weight-norm scale per out-channel (warp o)
    {
        float s = 0.0f;
        for (int i = lane; i < C_N * K_N; i += 32) {
            float x = v[o * C_N * K_N + i];
            s += x * x;
        }
        #pragma unroll
        for (int off = 16; off > 0; off >>= 1)
            s += __shfl_down_sync(0xffffffffu, s, off);
        if (lane == 0) osc[o] = gs[(l - 1) * C_N + o] * rsqrtf(s);
    }
    __syncthreads();

    // normalized weights + block max
    float m = 0.0f;
    for (int i = tid; i < 3200; i += 256) {
        float w = v[i] * osc[i / (C_N * K_N)];
        w_s[i] = w;
        m = fmaxf(m, fabsf(w));
    }
    #pragma unroll
    for (int off = 16; off > 0; off >>= 1)
        m = fmaxf(m, __shfl_down_sync(0xffffffffu, m, off));
    if (lane == 0) wred[o] = m;
    __syncthreads();
    if (tid == 0) {
        float wm = wred[0];
        #pragma unroll
        for (int i = 1; i < 8; i++) wm = fmaxf(wm, wred[i]);
        swmax = wm;
        g_wscale[l - 1] = wm / 16256.0f;
    }
    __syncthreads();

    if (tid < 32) {
        int oo = tid >> 2;
        int T = tid & 3;
        float inv = 16256.0f / swmax;
        for (int q = 0; q < 25; q++) {
            int k1 = 48 - 2 * q;   // tap_a (older row)
            int k2 = 49 - 2 * q;   // tap_b
            int ha[8], la[8], hb[8], lb[8];
            #pragma unroll
            for (int c = 0; c < 8; c++) {
                int W = __float2int_rn(w_s[oo * 400 + c * 50 + k1] * inv);
                ha[c] = (W + 64) >> 7;
                la[c] = W - (ha[c] << 7);
                W = __float2int_rn(w_s[oo * 400 + c * 50 + k2] * inv);
                hb[c] = (W + 64) >> 7;
                lb[c] = W - (hb[c] << 7);
            }
            u32 b0_2, b1_2;
            if (T < 2) {
                int c0 = 4 * T;
                b0_2 = pack4i(la[c0], la[c0+1], la[c0+2], la[c0+3]);
                b1_2 = pack4i(lb[c0], lb[c0+1], lb[c0+2], lb[c0+3]);
            } else {
                int c0 = 4 * (T - 2);
                b0_2 = pack4i(ha[c0], ha[c0+1], ha[c0+2], ha[c0+3]);
                b1_2 = pack4i(hb[c0], hb[c0+1], hb[c0+2], hb[c0+3]);
            }
            g_Bq[(size_t)(l - 1) * 800 + q * 32 + tid] = make_uint2(b0_2, b1_2);
        }
    }
}

// ---------------------------------------------------------------------------
// Layer 0 (scalar fp32; C_in = 1, dilation 1).  Records max|h'| -> g_hmax[1].
// ---------------------------------------------------------------------------
__global__ void __launch_bounds__(128)
layer0_kernel(const float* __restrict__ h_in, float* __restrict__ h_out,
              const float* __restrict__ bias, const float* __restrict__ gw,
              const float* __restrict__ gb) {
    constexpr int NP = 4;
    constexpr int TILE = 128 * NP;
    constexpr int HALO = K_N - 1;
    constexpr int HW = TILE + HALO;

    __shared__ __align__(16) float h_s[HW];
    __shared__ __align__(16) float w_s[K_N][C_N];
    __shared__ float gw_s[C_N][C_N];
    __shared__ float b_s[C_N];
    __shared__ float gb_s[C_N];

    const int b = blockIdx.y;
    const int tile0 = blockIdx.x * TILE;
    const int tid = threadIdx.x;

    for (int i = tid; i < K_N * C_N; i += 128) (&w_s[0][0])[i] = g_W0[i];
    for (int i = tid; i < C_N * C_N; i += 128) (&gw_s[0][0])[i] = gw[i];
    if (tid < C_N) { b_s[tid] = bias[tid]; gb_s[tid] = gb[tid]; }

    const float* hb = h_in + (size_t)b * T_LEN;
    for (int j = tid; j < HW; j += 128) {
        int t = tile0 - HALO + j;
        h_s[j] = (t >= 0) ? hb[t] : 0.0f;
    }
    __syncthreads();

    float acc[C_N][NP];
    #pragma unroll
    for (int o = 0; o < C_N; o++) {
        float bv = b_s[o];
        #pragma unroll
        for (int p = 0; p < NP; p++) acc[o][p] = bv;
    }

    #pragma unroll 1
    for (int k = 0; k < K_N; k++) {
        float hv[NP];
        #pragma unroll
        for (int p = 0; p < NP; p++) hv[p] = h_s[tid + k + p * 128];
        float wv[C_N];
        *(float4*)&wv[0] = *(const float4*)&w_s[k][0];
        *(float4*)&wv[4] = *(const float4*)&w_s[k][4];
        #pragma unroll
        for (int o = 0; o < C_N; o++)
            #pragma unroll
            for (int p = 0; p < NP; p++)
                acc[o][p] = fmaf(wv[o], hv[p], acc[o][p]);
    }

    float* ob = h_out + (size_t)b * C_N * T_LEN;
    u32 mx = 0;
    #pragma unroll
    for (int p = 0; p < NP; p++) {
        float prev = h_s[tid + HALO + p * 128];
        #pragma unroll
        for (int o = 0; o < C_N; o++) {
            float gate = gb_s[o];
            #pragma unroll
            for (int c = 0; c < C_N; c++) gate = fmaf(gw_s[o][c], acc[c][p], gate);
            float r = fast_tanh(acc[o][p]) * fast_sigmoid(gate) + prev;
            mx = max(mx, __float_as_uint(fabsf(r)));
            ob[(size_t)o * T_LEN + tile0 + tid + p * 128] = r;
        }
    }
    mx = __reduce_max_sync(0xffffffffu, mx);
    if ((tid & 31) == 0) atomicMax(&g_hmax_bits[1], mx);
}

// ---------------------------------------------------------------------------
// Layers 1..17: int8 m16n8k32 mma.sync, hi/lo packed into K.
// B fragments compressed to uint2; MMA1 operands derived via shfl(+2)/mask.
// SMEM: int8 tile (overlaid by park after MMA) + fp32 residual buffer.
// ---------------------------------------------------------------------------
template <int DIL>
__global__ void __launch_bounds__(128, 7)
layer_mma(const float* __restrict__ h_in, float* __restrict__ h_out,
          const uint2* __restrict__ Bq,    // [25][32] uint2
          const float* __restrict__ bias, const float* __restrict__ gw,
          const float* __restrict__ gb, int li) {
    constexpr int R = TILE_M / DIL;
    constexpr int R16 = R / 16;
    constexpr int PHROWS = R + 49;
    constexpr int TROWS = TILE_M + 49 * DIL;
    constexpr int PARKPAD = 9;
    constexpr int TILEB = TROWS * 16;
    constexpr int PARKB = TILE_M * PARKPAD * 4;
    constexpr int R1 = (((TILEB > PARKB) ? TILEB : PARKB) + 15) & ~15;

    extern __shared__ __align__(16) char dyn[];
    char* tile = dyn;                      // int8 tile [TROWS][16]
    float* park = (float*)dyn;             // overlay after MMA
    float* f32res = (float*)(dyn + R1);    // fp32 residual [TILE_M][8]
    __shared__ float ctrl[80];             // bias[8], gb[8], gw[64]

    const int b = blockIdx.y;
    const int tile0 = blockIdx.x * TILE_M;
    const int tid = threadIdx.x;
    const int wid = tid >> 5;
    const int lane = tid & 31;

    if (tid < 8) ctrl[tid] = bias[tid];
    else if (tid < 16) ctrl[tid] = gb[tid - 8];
    else if (tid < 80) ctrl[tid] = gw[tid - 16];

    const float hmax = __uint_as_float(g_hmax_bits[li]);
    const float inv_s = 16256.0f / hmax;
    const float s_h = hmax / 16256.0f;
    const float s_w = g_wscale[li - 1];

    // Stage quantized tile, phase-major; one thread per time row (STS.128).
    // Tile rows (r >= 0) also parked as fp32 for the epilogue residual.
    const float* hb = h_in + (size_t)b * C_N * T_LEN;
    for (int j = tid; j < TROWS; j += 128) {
        int t = tile0 - 49 * DIL + j;
        float v[C_N];
        int Hh[8], Hl[8];
        #pragma unroll
        for (int c = 0; c < C_N; c++) {
            v[c] = (t >= 0) ? hb[(size_t)c * T_LEN + t] : 0.0f;
            int H = __float2int_rn(v[c] * inv_s);
            Hh[c] = (H + 64) >> 7;
            Hl[c] = H - (Hh[c] << 7);
        }
        int row = j / DIL;
        int p = j % DIL;
        uint4 w;
        w.x = pack4i(Hh[0], Hh[1], Hh[2], Hh[3]);
        w.y = pack4i(Hh[4], Hh[5], Hh[6], Hh[7]);
        w.z = pack4i(Hl[0], Hl[1], Hl[2], Hl[3]);
        w.w = pack4i(Hl[4], Hl[5], Hl[6], Hl[7]);
        *(uint4*)&tile[(p * PHROWS + row) * 16] = w;
        int r = j - 49 * DIL;
        if (r >= 0) {
            *(float4*)&f32res[r * 8] = make_float4(v[0], v[1], v[2], v[3]);
            *(float4*)&f32res[r * 8 + 4] = make_float4(v[4], v[5], v[6], v[7]);
        }
    }
    __syncthreads();

    // Per-z ldmatrix base offsets (16B rows).
    const int rowlane = (lane & 15) + (lane >> 4);
    u32 zb[4];
    #pragma unroll
    for (int z = 0; z < 4; z++) {
        int st = wid * 4 + z;
        int p = st / R16;
        int sub = st % R16;
        zb[z] = (u32)((p * PHROWS + sub * 16 + 48 + rowlane) * 16);
    }

    const u32 t32 = smem_u32(tile);
    const bool hiLane = (lane & 3) < 2;

    int acc1[4][4], acc2[4][4];
    #pragma unroll
    for (int z = 0; z < 4; z++)
        #pragma unroll
        for (int q = 0; q < 4; q++) { acc1[z][q] = 0; acc2[z][q] = 0; }

    {
        const uint2* bw = Bq + lane;
        uint2 bb = *bw;                      // prefetch q=0
        #pragma unroll 5
        for (int q = 0; q < 25; q++) {
            uint2 nb = (q < 24) ? bw[(q + 1) * 32] : bb;
            // Derive MMA1 operands ([Whi,0] pattern) from lane+2's (Wlo,Whi) pair.
            u32 m1x = __shfl_sync(0xffffffffu, bb.x, (lane + 2) & 31);
            u32 m1y = __shfl_sync(0xffffffffu, bb.y, (lane + 2) & 31);
            m1x = hiLane ? m1x : 0u;
            m1y = hiLane ? m1y : 0u;
            u32 off = (u32)(q * 32);
            #pragma unroll
            for (int z = 0; z < 4; z++) {
                u32 a0, a1, a2, a3;
                ldmA(a0, a1, a2, a3, t32 + zb[z] - off);
                mma_s8(acc1[z], a0, a1, a2, a3, m1x, m1y);
                mma_s8(acc2[z], a0, a1, a2, a3, bb.x, bb.y);
            }
            bb = nb;
        }
    }

    // Park combined fp32 conv outputs (overlay on tile).
    const float c1 = s_h * s_w * 16384.0f;
    const float c2 = s_h * s_w * 128.0f;
    __syncthreads();
    {
        const int g = lane >> 2;
        const int tig = lane & 3;
        #pragma unroll
        for (int z = 0; z < 4; z++) {
            int st = wid * 4 + z;
            int p = st / R16;
            int sub = st % R16;
            int i0 = (sub * 16 + g) * DIL + p;
            int i1 = i0 + 8 * DIL;
            park[i0 * PARKPAD + 2 * tig]     = c1 * (float)acc1[z][0] + c2 * (float)acc2[z][0];
            park[i0 * PARKPAD + 2 * tig + 1] = c1 * (float)acc1[z][1] + c2 * (float)acc2[z][1];
            park[i1 * PARKPAD + 2 * tig]     = c1 * (float)acc1[z][2] + c2 * (float)acc2[z][2];
            park[i1 * PARKPAD + 2 * tig + 1] = c1 * (float)acc1[z][3] + c2 * (float)acc2[z][3];
        }
    }
    __syncthreads();

    // Epilogue: rows tid and tid+128; residual from SMEM; track out max.
    float* ob = h_out + (size_t)b * C_N * T_LEN;
    u32 mx = 0;
    #pragma unroll
    for (int half = 0; half < 2; half++) {
        const int r = tid + half * 128;
        float outv[C_N];
        #pragma unroll
        for (int o = 0; o < C_N; o++) outv[o] = park[r * PARKPAD + o] + ctrl[o];
        float4 p0 = *(const float4*)&f32res[r * 8];
        float4 p1 = *(const float4*)&f32res[r * 8 + 4];
        float prev[C_N] = {p0.x, p0.y, p0.z, p0.w, p1.x, p1.y, p1.z, p1.w};
        #pragma unroll
        for (int o = 0; o < C_N; o++) {
            float gate = ctrl[8 + o];
            #pragma unroll
            for (int c = 0; c < C_N; c++)
                gate = fmaf(ctrl[16 + o * 8 + c], outv[c], gate);
            float rr = fast_tanh(outv[o]) * fast_sigmoid(gate) + prev[o];
            mx = max(mx, __float_as_uint(fabsf(rr)));
            ob[(size_t)o * T_LEN + tile0 + r] = rr;
        }
    }
    mx = __reduce_max_sync(0xffffffffu, mx);
    if (lane == 0) atomicMax(&g_hmax_bits[li + 1], mx);
}

// ---------------------------------------------------------------------------
// Head
// ---------------------------------------------------------------------------
__global__ void __launch_bounds__(256)
head_kernel(const float* __restrict__ h,
            const float* __restrict__ mean_w, const float* __restrict__ mean_b,
            const float* __restrict__ lv_w, const float* __restrict__ lv_b,
            float* __restrict__ out) {
    const int b = blockIdx.y;
    const int t0 = (blockIdx.x * 256 + threadIdx.x) * 4;
    if (t0 >= T_LEN) return;
    const float* hbp = h + (size_t)b * C_N * T_LEN;
    float m[4], lv[4];
    float mb = mean_b[0], lb = lv_b[0];
    #pragma unroll
    for (int p = 0; p < 4; p++) { m[p] = mb; lv[p] = lb; }
    #pragma unroll
    for (int c = 0; c < C_N; c++) {
        float4 hv = *(const float4*)&hbp[(size_t)c * T_LEN + t0];
        float mw = mean_w[c], lw = lv_w[c];
        m[0] = fmaf(mw, hv.x, m[0]); lv[0] = fmaf(lw, hv.x, lv[0]);
        m[1] = fmaf(mw, hv.y, m[1]); lv[1] = fmaf(lw, hv.y, lv[1]);
        m[2] = fmaf(mw, hv.z, m[2]); lv[2] = fmaf(lw, hv.z, lv[2]);
        m[3] = fmaf(mw, hv.w, m[3]); lv[3] = fmaf(lw, hv.w, lv[3]);
    }
    float s[4];
    #pragma unroll
    for (int p = 0; p < 4; p++) s[p] = expf(0.5f * lv[p]);
    *(float4*)&out[(size_t)b * T_LEN + t0] = make_float4(m[0], m[1], m[2], m[3]);
    *(float4*)&out[(size_t)B_N * T_LEN + (size_t)b * T_LEN + t0] =
        make_float4(s[0], s[1], s[2], s[3]);
}

// ---------------------------------------------------------------------------
static int smem_for_dil(int d) {
    int tileb = (TILE_M + 49 * d) * 16;
    int parkb = TILE_M * 9 * 4;
    int r1 = (tileb > parkb ? tileb : parkb);
    r1 = (r1 + 15) & ~15;
    return r1 + TILE_M * 8 * 4;            // + fp32 residual buffer
}

extern "C" void kernel_launch(void* const* d_in, const int* in_sizes, int n_in,
                              void* d_out, int out_size) {
    (void)in_sizes; (void)n_in; (void)out_size;
    const float* x      = (const float*)d_in[0];
    const float* v0     = (const float*)d_in[1];
    const float* g0     = (const float*)d_in[2];
    const float* b0     = (const float*)d_in[3];
    const float* gw0    = (const float*)d_in[4];
    const float* gb0    = (const float*)d_in[5];
    const float* vs     = (const float*)d_in[6];
    const float* gs     = (const float*)d_in[7];
    const float* bs     = (const float*)d_in[8];
    const float* gws    = (const float*)d_in[9];
    const float* gbs    = (const float*)d_in[10];
    const float* mean_w = (const float*)d_in[11];
    const float* mean_b = (const float*)d_in[12];
    const float* lv_w   = (const float*)d_in[13];
    const float* lv_b   = (const float*)d_in[14];

    float *bufA, *bufB;
    uint2* Bq;
    cudaGetSymbolAddress((void**)&bufA, g_h0);
    cudaGetSymbolAddress((void**)&bufB, g_h1);
    cudaGetSymbolAddress((void**)&Bq, g_Bq);

    cudaFuncSetAttribute(layer_mma<1>, cudaFuncAttributeMaxDynamicSharedMemorySize, smem_for_dil(1));
    cudaFuncSetAttribute(layer_mma<2>, cudaFuncAttributeMaxDynamicSharedMemorySize, smem_for_dil(2));
    cudaFuncSetAttribute(layer_mma<4>, cudaFuncAttributeMaxDynamicSharedMemorySize, smem_for_dil(4));
    cudaFuncSetAttribute(layer_mma<8>, cudaFuncAttributeMaxDynamicSharedMemorySize, smem_for_dil(8));

    prep_weights<<<18, 256>>>(v0, g0, vs, gs);

    layer0_kernel<<<dim3(T_LEN / 512, B_N), 128>>>(x, bufA, b0, gw0, gb0);

    static const int dils[18] = {1,1,1,1,1,1,1,2,2,2,2,4,4,4,4,8,8,8};
    dim3 grid(T_LEN / TILE_M, B_N);
    float* cur = bufA;
    float* nxt = bufB;
    for (int i = 1; i < 18; i++) {
        const uint2* Wl  = Bq + (size_t)(i - 1) * 800;
        const float* bl  = bs  + (i - 1) * C_N;
        const float* gwl = gws + (i - 1) * C_N * C_N;
        const float* gbl = gbs + (i - 1) * C_N;
        switch (dils[i]) {
            case 1: layer_mma<1><<<grid, 128, smem_for_dil(1)>>>(cur, nxt, Wl, bl, gwl, gbl, i); break;
            case 2: layer_mma<2><<<grid, 128, smem_for_dil(2)>>>(cur, nxt, Wl, bl, gwl, gbl, i); break;
            case 4: layer_mma<4><<<grid, 128, smem_for_dil(4)>>>(cur, nxt, Wl, bl, gwl, gbl, i); break;
            case 8: layer_mma<8><<<grid, 128, smem_for_dil(8)>>>(cur, nxt, Wl, bl, gwl, gbl, i); break;
        }
        float* t = cur; cur = nxt; nxt = t;
    }

    head_kernel<<<dim3(T_LEN / (256 * 4), B_N), 256>>>(
        cur, mean_w, mean_b, lv_w, lv_b, (float*)d_out);
}

// round 14
// speedup vs baseline: 4.7780x; 1.1088x over previous
#include <cuda_runtime.h>
#include <cuda_bf16.h>
#include <math.h>
#include <stdint.h>

typedef uint32_t u32;
typedef uint64_t u64;

#define T_LEN 262144
#define B_N 8
#define C_N 8
#define K_N 50
#define TILE_M 256

// Ping-pong hidden state [B][C][T]
__device__ float g_h0[B_N * C_N * T_LEN];
__device__ float g_h1[B_N * C_N * T_LEN];
// Layer-0 scalar weights [k][o]
__device__ float g_W0[K_N * C_N];
// Layers 1..17 int8 B fragments (compressed): [layer][q(25)][lane(32)] uint2 = (b0_2,b1_2)
// MMA1's operands are derived in-kernel via shfl from lane+2 (zero on (lane&3)>=2).
__device__ uint2 g_Bq[17 * 25 * 32];
__device__ float g_wscale[17];
// |h| max bit-patterns; g_hmax_bits[i] = max |input of mma-layer i| (written by layer i-1)
__device__ unsigned int g_hmax_bits[19];

// ---------------------------------------------------------------------------
__device__ __forceinline__ u32 smem_u32(const void* p) {
    return (u32)__cvta_generic_to_shared(p);
}
__device__ __forceinline__ void ldmA(u32& a0, u32& a1, u32& a2, u32& a3, u32 addr) {
    asm volatile("ldmatrix.sync.aligned.m8n8.x4.shared.b16 {%0,%1,%2,%3}, [%4];"
                 : "=r"(a0), "=r"(a1), "=r"(a2), "=r"(a3) : "r"(addr));
}
__device__ __forceinline__ void mma_s8(int* c, u32 a0, u32 a1, u32 a2, u32 a3,
                                       u32 b0, u32 b1) {
    asm volatile("mma.sync.aligned.m16n8k32.row.col.s32.s8.s8.s32 "
                 "{%0,%1,%2,%3},{%4,%5,%6,%7},{%8,%9},{%0,%1,%2,%3};"
                 : "+r"(c[0]), "+r"(c[1]), "+r"(c[2]), "+r"(c[3])
                 : "r"(a0), "r"(a1), "r"(a2), "r"(a3), "r"(b0), "r"(b1));
}
__device__ __forceinline__ u32 pack4i(int a, int b, int c, int d) {
    return (u32)(a & 0xff) | ((u32)(b & 0xff) << 8) |
           ((u32)(c & 0xff) << 16) | ((u32)(d & 0xff) << 24);
}
// tanh(x)*sigmoid(g) with ONE fast division:
//   e=exp(-2x), f=exp(-g)  ->  (1-e) / ((1+e)*(1+f))
// clamp +-20: denominator <= (1+e^40)^2 ~ 5.3e34 < 2^126, fdividef valid.
__device__ __forceinline__ float gated_act(float x, float g) {
    x = fminf(fmaxf(x, -20.0f), 20.0f);
    g = fminf(fmaxf(g, -20.0f), 20.0f);
    float e = __expf(-2.0f * x);
    float f = __expf(-g);
    return __fdividef(1.0f - e, (1.0f + e) * (1.0f + f));
}

// ---------------------------------------------------------------------------
// Weight prep. Block per layer.  l=0: scalar fp32 weights.  l>=1: weight-norm,
// per-layer wmax, 15-bit hi/lo int8 quantization, pack MMA B fragments.
// Stored (compressed): (b0_2,b1_2) = lanes T<2: (lo taps), T>=2: (hi taps).
// MMA1 B (= [Whi,0]) is reconstructed in-kernel: shfl from lane+2, mask T>=2.
// ---------------------------------------------------------------------------
__global__ void prep_weights(const float* __restrict__ v0,
                             const float* __restrict__ g0,
                             const float* __restrict__ vs,
                             const float* __restrict__ gs) {
    int l = blockIdx.x;
    int tid = threadIdx.x;

    if (l == 0) {
        if (tid < C_N) {
            int o = tid;
            float s = 0.0f;
            for (int k = 0; k < K_N; k++) {
                float x = v0[o * K_N + k];
                s += x * x;
            }
            float scale = g0[o] * rsqrtf(s);
            for (int k = 0; k < K_N; k++)
                g_W0[k * C_N + o] = scale * v0[o * K_N + k];
        }
        return;
    }

    __shared__ float osc[C_N];
    __shared__ float w_s[C_N * C_N * K_N];   // 3200 floats
    __shared__ float wred[8];
    __shared__ float swmax;

    const float* v = vs + (size_t)(l - 1) * C_N * C_N * K_N;
    int o = tid >> 5;
    int lane = tid & 31;

    // weight-norm scale per out-channel (warp o)
    {
        float s = 0.0f;
        for (int i = lane; i < C_N * K_N; i += 32) {
            float x = v[o * C_N * K_N + i];
            s += x * x;
        }
        #pragma unroll
        for (int off = 16; off > 0; off >>= 1)
            s += __shfl_down_sync(0xffffffffu, s, off);
        if (lane == 0) osc[o] = gs[(l - 1) * C_N + o] * rsqrtf(s);
    }
    __syncthreads();

    // normalized weights + block max
    float m = 0.0f;
    for (int i = tid; i < 3200; i += 256) {
        float w = v[i] * osc[i / (C_N * K_N)];
        w_s[i] = w;
        m = fmaxf(m, fabsf(w));
    }
    #pragma unroll
    for (int off = 16; off > 0; off >>= 1)
        m = fmaxf(m, __shfl_down_sync(0xffffffffu, m, off));
    if (lane == 0) wred[o] = m;
    __syncthreads();
    if (tid == 0) {
        float wm = wred[0];
        #pragma unroll
        for (int i = 1; i < 8; i++) wm = fmaxf(wm, wred[i]);
        swmax = wm;
        g_wscale[l - 1] = wm / 16256.0f;
    }
    __syncthreads();

    if (tid < 32) {
        int oo = tid >> 2;
        int T = tid & 3;
        float inv = 16256.0f / swmax;
        for (int q = 0; q < 25; q++) {
            int k1 = 48 - 2 * q;   // tap_a (older row)
            int k2 = 49 - 2 * q;   // tap_b
            int ha[8], la[8], hb[8], lb[8];
            #pragma unroll
            for (int c = 0; c < 8; c++) {
                int W = __float2int_rn(w_s[oo * 400 + c * 50 + k1] * inv);
                ha[c] = (W + 64) >> 7;
                la[c] = W - (ha[c] << 7);
                W = __float2int_rn(w_s[oo * 400 + c * 50 + k2] * inv);
                hb[c] = (W + 64) >> 7;
                lb[c] = W - (hb[c] << 7);
            }
            u32 b0_2, b1_2;
            if (T < 2) {
                int c0 = 4 * T;
                b0_2 = pack4i(la[c0], la[c0+1], la[c0+2], la[c0+3]);
                b1_2 = pack4i(lb[c0], lb[c0+1], lb[c0+2], lb[c0+3]);
            } else {
                int c0 = 4 * (T - 2);
                b0_2 = pack4i(ha[c0], ha[c0+1], ha[c0+2], ha[c0+3]);
                b1_2 = pack4i(hb[c0], hb[c0+1], hb[c0+2], hb[c0+3]);
            }
            g_Bq[(size_t)(l - 1) * 800 + q * 32 + tid] = make_uint2(b0_2, b1_2);
        }
    }
}

// ---------------------------------------------------------------------------
// Layer 0 (scalar fp32; C_in = 1, dilation 1).  Records max|h'| -> g_hmax[1].
// ---------------------------------------------------------------------------
__global__ void __launch_bounds__(128)
layer0_kernel(const float* __restrict__ h_in, float* __restrict__ h_out,
              const float* __restrict__ bias, const float* __restrict__ gw,
              const float* __restrict__ gb) {
    constexpr int NP = 4;
    constexpr int TILE = 128 * NP;
    constexpr int HALO = K_N - 1;
    constexpr int HW = TILE + HALO;

    __shared__ __align__(16) float h_s[HW];
    __shared__ __align__(16) float w_s[K_N][C_N];
    __shared__ float gw_s[C_N][C_N];
    __shared__ float b_s[C_N];
    __shared__ float gb_s[C_N];

    const int b = blockIdx.y;
    const int tile0 = blockIdx.x * TILE;
    const int tid = threadIdx.x;

    for (int i = tid; i < K_N * C_N; i += 128) (&w_s[0][0])[i] = g_W0[i];
    for (int i = tid; i < C_N * C_N; i += 128) (&gw_s[0][0])[i] = gw[i];
    if (tid < C_N) { b_s[tid] = bias[tid]; gb_s[tid] = gb[tid]; }

    const float* hb = h_in + (size_t)b * T_LEN;
    for (int j = tid; j < HW; j += 128) {
        int t = tile0 - HALO + j;
        h_s[j] = (t >= 0) ? hb[t] : 0.0f;
    }
    __syncthreads();

    float acc[C_N][NP];
    #pragma unroll
    for (int o = 0; o < C_N; o++) {
        float bv = b_s[o];
        #pragma unroll
        for (int p = 0; p < NP; p++) acc[o][p] = bv;
    }

    #pragma unroll 1
    for (int k = 0; k < K_N; k++) {
        float hv[NP];
        #pragma unroll
        for (int p = 0; p < NP; p++) hv[p] = h_s[tid + k + p * 128];
        float wv[C_N];
        *(float4*)&wv[0] = *(const float4*)&w_s[k][0];
        *(float4*)&wv[4] = *(const float4*)&w_s[k][4];
        #pragma unroll
        for (int o = 0; o < C_N; o++)
            #pragma unroll
            for (int p = 0; p < NP; p++)
                acc[o][p] = fmaf(wv[o], hv[p], acc[o][p]);
    }

    float* ob = h_out + (size_t)b * C_N * T_LEN;
    u32 mx = 0;
    #pragma unroll
    for (int p = 0; p < NP; p++) {
        float prev = h_s[tid + HALO + p * 128];
        #pragma unroll
        for (int o = 0; o < C_N; o++) {
            float gate = gb_s[o];
            #pragma unroll
            for (int c = 0; c < C_N; c++) gate = fmaf(gw_s[o][c], acc[c][p], gate);
            float r = gated_act(acc[o][p], gate) + prev;
            mx = max(mx, __float_as_uint(fabsf(r)));
            ob[(size_t)o * T_LEN + tile0 + tid + p * 128] = r;
        }
    }
    mx = __reduce_max_sync(0xffffffffu, mx);
    if ((tid & 31) == 0) atomicMax(&g_hmax_bits[1], mx);
}

// ---------------------------------------------------------------------------
// Layers 1..17: int8 m16n8k32 mma.sync, hi/lo packed into K.
// B fragments compressed to uint2; MMA1 operands derived via shfl(+2)/mask.
// SMEM: int8 tile (overlaid by park after MMA) + fp32 residual buffer.
// ---------------------------------------------------------------------------
template <int DIL>
__global__ void __launch_bounds__(128, 7)
layer_mma(const float* __restrict__ h_in, float* __restrict__ h_out,
          const uint2* __restrict__ Bq,    // [25][32] uint2
          const float* __restrict__ bias, const float* __restrict__ gw,
          const float* __restrict__ gb, int li) {
    constexpr int R = TILE_M / DIL;
    constexpr int R16 = R / 16;
    constexpr int PHROWS = R + 49;
    constexpr int TROWS = TILE_M + 49 * DIL;
    constexpr int PARKPAD = 9;
    constexpr int TILEB = TROWS * 16;
    constexpr int PARKB = TILE_M * PARKPAD * 4;
    constexpr int R1 = (((TILEB > PARKB) ? TILEB : PARKB) + 15) & ~15;

    extern __shared__ __align__(16) char dyn[];
    char* tile = dyn;                      // int8 tile [TROWS][16]
    float* park = (float*)dyn;             // overlay after MMA
    float* f32res = (float*)(dyn + R1);    // fp32 residual [TILE_M][8]
    __shared__ float ctrl[80];             // bias[8], gb[8], gw[64]

    const int b = blockIdx.y;
    const int tile0 = blockIdx.x * TILE_M;
    const int tid = threadIdx.x;
    const int wid = tid >> 5;
    const int lane = tid & 31;

    if (tid < 8) ctrl[tid] = bias[tid];
    else if (tid < 16) ctrl[tid] = gb[tid - 8];
    else if (tid < 80) ctrl[tid] = gw[tid - 16];

    const float hmax = __uint_as_float(g_hmax_bits[li]);
    const float inv_s = 16256.0f / hmax;
    const float s_h = hmax / 16256.0f;
    const float s_w = g_wscale[li - 1];

    // Stage quantized tile, phase-major; one thread per time row (STS.128).
    // Tile rows (r >= 0) also parked as fp32 for the epilogue residual.
    const float* hb = h_in + (size_t)b * C_N * T_LEN;
    for (int j = tid; j < TROWS; j += 128) {
        int t = tile0 - 49 * DIL + j;
        float v[C_N];
        int Hh[8], Hl[8];
        #pragma unroll
        for (int c = 0; c < C_N; c++) {
            v[c] = (t >= 0) ? hb[(size_t)c * T_LEN + t] : 0.0f;
            int H = __float2int_rn(v[c] * inv_s);
            Hh[c] = (H + 64) >> 7;
            Hl[c] = H - (Hh[c] << 7);
        }
        int row = j / DIL;
        int p = j % DIL;
        uint4 w;
        w.x = pack4i(Hh[0], Hh[1], Hh[2], Hh[3]);
        w.y = pack4i(Hh[4], Hh[5], Hh[6], Hh[7]);
        w.z = pack4i(Hl[0], Hl[1], Hl[2], Hl[3]);
        w.w = pack4i(Hl[4], Hl[5], Hl[6], Hl[7]);
        *(uint4*)&tile[(p * PHROWS + row) * 16] = w;
        int r = j - 49 * DIL;
        if (r >= 0) {
            *(float4*)&f32res[r * 8] = make_float4(v[0], v[1], v[2], v[3]);
            *(float4*)&f32res[r * 8 + 4] = make_float4(v[4], v[5], v[6], v[7]);
        }
    }
    __syncthreads();

    // Per-z ldmatrix base offsets (16B rows).
    const int rowlane = (lane & 15) + (lane >> 4);
    u32 zb[4];
    #pragma unroll
    for (int z = 0; z < 4; z++) {
        int st = wid * 4 + z;
        int p = st / R16;
        int sub = st % R16;
        zb[z] = (u32)((p * PHROWS + sub * 16 + 48 + rowlane) * 16);
    }

    const u32 t32 = smem_u32(tile);
    const bool hiLane = (lane & 3) < 2;

    int acc1[4][4], acc2[4][4];
    #pragma unroll
    for (int z = 0; z < 4; z++)
        #pragma unroll
        for (int q = 0; q < 4; q++) { acc1[z][q] = 0; acc2[z][q] = 0; }

    {
        const uint2* bw = Bq + lane;
        uint2 bb = *bw;                      // prefetch q=0
        #pragma unroll 5
        for (int q = 0; q < 25; q++) {
            uint2 nb = (q < 24) ? bw[(q + 1) * 32] : bb;
            // Derive MMA1 operands ([Whi,0] pattern) from lane+2's (Wlo,Whi) pair.
            u32 m1x = __shfl_sync(0xffffffffu, bb.x, (lane + 2) & 31);
            u32 m1y = __shfl_sync(0xffffffffu, bb.y, (lane + 2) & 31);
            m1x = hiLane ? m1x : 0u;
            m1y = hiLane ? m1y : 0u;
            u32 off = (u32)(q * 32);
            #pragma unroll
            for (int z = 0; z < 4; z++) {
                u32 a0, a1, a2, a3;
                ldmA(a0, a1, a2, a3, t32 + zb[z] - off);
                mma_s8(acc1[z], a0, a1, a2, a3, m1x, m1y);
                mma_s8(acc2[z], a0, a1, a2, a3, bb.x, bb.y);
            }
            bb = nb;
        }
    }

    // Park combined fp32 conv outputs (overlay on tile).
    const float c1 = s_h * s_w * 16384.0f;
    const float c2 = s_h * s_w * 128.0f;
    __syncthreads();
    {
        const int g = lane >> 2;
        const int tig = lane & 3;
        #pragma unroll
        for (int z = 0; z < 4; z++) {
            int st = wid * 4 + z;
            int p = st / R16;
            int sub = st % R16;
            int i0 = (sub * 16 + g) * DIL + p;
            int i1 = i0 + 8 * DIL;
            park[i0 * PARKPAD + 2 * tig]     = c1 * (float)acc1[z][0] + c2 * (float)acc2[z][0];
            park[i0 * PARKPAD + 2 * tig + 1] = c1 * (float)acc1[z][1] + c2 * (float)acc2[z][1];
            park[i1 * PARKPAD + 2 * tig]     = c1 * (float)acc1[z][2] + c2 * (float)acc2[z][2];
            park[i1 * PARKPAD + 2 * tig + 1] = c1 * (float)acc1[z][3] + c2 * (float)acc2[z][3];
        }
    }
    __syncthreads();

    // Epilogue: rows tid and tid+128; residual from SMEM; track out max.
    float* ob = h_out + (size_t)b * C_N * T_LEN;
    u32 mx = 0;
    #pragma unroll
    for (int half = 0; half < 2; half++) {
        const int r = tid + half * 128;
        float outv[C_N];
        #pragma unroll
        for (int o = 0; o < C_N; o++) outv[o] = park[r * PARKPAD + o] + ctrl[o];
        float4 p0 = *(const float4*)&f32res[r * 8];
        float4 p1 = *(const float4*)&f32res[r * 8 + 4];
        float prev[C_N] = {p0.x, p0.y, p0.z, p0.w, p1.x, p1.y, p1.z, p1.w};
        #pragma unroll
        for (int o = 0; o < C_N; o++) {
            float gate = ctrl[8 + o];
            #pragma unroll
            for (int c = 0; c < C_N; c++)
                gate = fmaf(ctrl[16 + o * 8 + c], outv[c], gate);
            float rr = gated_act(outv[o], gate) + prev[o];
            mx = max(mx, __float_as_uint(fabsf(rr)));
            ob[(size_t)o * T_LEN + tile0 + r] = rr;
        }
    }
    mx = __reduce_max_sync(0xffffffffu, mx);
    if (lane == 0) atomicMax(&g_hmax_bits[li + 1], mx);
}

// ---------------------------------------------------------------------------
// Head
// ---------------------------------------------------------------------------
__global__ void __launch_bounds__(256)
head_kernel(const float* __restrict__ h,
            const float* __restrict__ mean_w, const float* __restrict__ mean_b,
            const float* __restrict__ lv_w, const float* __restrict__ lv_b,
            float* __restrict__ out) {
    const int b = blockIdx.y;
    const int t0 = (blockIdx.x * 256 + threadIdx.x) * 4;
    if (t0 >= T_LEN) return;
    const float* hbp = h + (size_t)b * C_N * T_LEN;
    float m[4], lv[4];
    float mb = mean_b[0], lb = lv_b[0];
    #pragma unroll
    for (int p = 0; p < 4; p++) { m[p] = mb; lv[p] = lb; }
    #pragma unroll
    for (int c = 0; c < C_N; c++) {
        float4 hv = *(const float4*)&hbp[(size_t)c * T_LEN + t0];
        float mw = mean_w[c], lw = lv_w[c];
        m[0] = fmaf(mw, hv.x, m[0]); lv[0] = fmaf(lw, hv.x, lv[0]);
        m[1] = fmaf(mw, hv.y, m[1]); lv[1] = fmaf(lw, hv.y, lv[1]);
        m[2] = fmaf(mw, hv.z, m[2]); lv[2] = fmaf(lw, hv.z, lv[2]);
        m[3] = fmaf(mw, hv.w, m[3]); lv[3] = fmaf(lw, hv.w, lv[3]);
    }
    float s[4];
    #pragma unroll
    for (int p = 0; p < 4; p++) s[p] = expf(0.5f * lv[p]);
    *(float4*)&out[(size_t)b * T_LEN + t0] = make_float4(m[0], m[1], m[2], m[3]);
    *(float4*)&out[(size_t)B_N * T_LEN + (size_t)b * T_LEN + t0] =
        make_float4(s[0], s[1], s[2], s[3]);
}

// ---------------------------------------------------------------------------
static int smem_for_dil(int d) {
    int tileb = (TILE_M + 49 * d) * 16;
    int parkb = TILE_M * 9 * 4;
    int r1 = (tileb > parkb ? tileb : parkb);
    r1 = (r1 + 15) & ~15;
    return r1 + TILE_M * 8 * 4;            // + fp32 residual buffer
}

extern "C" void kernel_launch(void* const* d_in, const int* in_sizes, int n_in,
                              void* d_out, int out_size) {
    (void)in_sizes; (void)n_in; (void)out_size;
    const float* x      = (const float*)d_in[0];
    const float* v0     = (const float*)d_in[1];
    const float* g0     = (const float*)d_in[2];
    const float* b0     = (const float*)d_in[3];
    const float* gw0    = (const float*)d_in[4];
    const float* gb0    = (const float*)d_in[5];
    const float* vs     = (const float*)d_in[6];
    const float* gs     = (const float*)d_in[7];
    const float* bs     = (const float*)d_in[8];
    const float* gws    = (const float*)d_in[9];
    const float* gbs    = (const float*)d_in[10];
    const float* mean_w = (const float*)d_in[11];
    const float* mean_b = (const float*)d_in[12];
    const float* lv_w   = (const float*)d_in[13];
    const float* lv_b   = (const float*)d_in[14];

    float *bufA, *bufB;
    uint2* Bq;
    cudaGetSymbolAddress((void**)&bufA, g_h0);
    cudaGetSymbolAddress((void**)&bufB, g_h1);
    cudaGetSymbolAddress((void**)&Bq, g_Bq);

    cudaFuncSetAttribute(layer_mma<1>, cudaFuncAttributeMaxDynamicSharedMemorySize, smem_for_dil(1));
    cudaFuncSetAttribute(layer_mma<2>, cudaFuncAttributeMaxDynamicSharedMemorySize, smem_for_dil(2));
    cudaFuncSetAttribute(layer_mma<4>, cudaFuncAttributeMaxDynamicSharedMemorySize, smem_for_dil(4));
    cudaFuncSetAttribute(layer_mma<8>, cudaFuncAttributeMaxDynamicSharedMemorySize, smem_for_dil(8));

    prep_weights<<<18, 256>>>(v0, g0, vs, gs);

    layer0_kernel<<<dim3(T_LEN / 512, B_N), 128>>>(x, bufA, b0, gw0, gb0);

    static const int dils[18] = {1,1,1,1,1,1,1,2,2,2,2,4,4,4,4,8,8,8};
    dim3 grid(T_LEN / TILE_M, B_N);
    float* cur = bufA;
    float* nxt = bufB;
    for (int i = 1; i < 18; i++) {
        const uint2* Wl  = Bq + (size_t)(i - 1) * 800;
        const float* bl  = bs  + (i - 1) * C_N;
        const float* gwl = gws + (i - 1) * C_N * C_N;
        const float* gbl = gbs + (i - 1) * C_N;
        switch (dils[i]) {
            case 1: layer_mma<1><<<grid, 128, smem_for_dil(1)>>>(cur, nxt, Wl, bl, gwl, gbl, i); break;
            case 2: layer_mma<2><<<grid, 128, smem_for_dil(2)>>>(cur, nxt, Wl, bl, gwl, gbl, i); break;
            case 4: layer_mma<4><<<grid, 128, smem_for_dil(4)>>>(cur, nxt, Wl, bl, gwl, gbl, i); break;
            case 8: layer_mma<8><<<grid, 128, smem_for_dil(8)>>>(cur, nxt, Wl, bl, gwl, gbl, i); break;
        }
        float* t = cur; cur = nxt; nxt = t;
    }

    head_kernel<<<dim3(T_LEN / (256 * 4), B_N), 256>>>(
        cur, mean_w, mean_b, lv_w, lv_b, (float*)d_out);
}